// round 2
// baseline (speedup 1.0000x reference)
#include <cuda_runtime.h>

#define NN 100000
#define NE 1600000
#define H  64

// ---------------- scratch (device globals; no allocation) ----------------
__device__ float g_ew[1600000ull * 64];   // edge weights, CSR-slot order [E,64]
__device__ int   g_cnt[NN];
__device__ int   g_off[NN + 1];
__device__ int   g_cur[NN];
__device__ int   g_src[NE];
__device__ int   g_eid[NE];
__device__ float g_xlin[NN * H];
__device__ float g_dinv[NN * H];
__device__ float g_y[NN * H];
__device__ float g_hagg[NN * H];
__device__ float g_h[NN * H];

// ---------------- CSR build ----------------
__global__ void k_zero() {
    int i = blockIdx.x * blockDim.x + threadIdx.x;
    if (i < NN) g_cnt[i] = 0;
}

// edge_index delivered as int32 [2, E]: row 0 = src, row 1 = dst
__global__ void k_count(const int* __restrict__ ei) {
    int e = blockIdx.x * blockDim.x + threadIdx.x;
    if (e < NE) {
        int c = ei[NE + e];
        if ((unsigned)c < (unsigned)NN) atomicAdd(&g_cnt[c], 1);
    }
}

__global__ void k_scan() {
    __shared__ int s[1024];
    int t = threadIdx.x;
    const int C = (NN + 1023) / 1024;
    int start = t * C; if (start > NN) start = NN;
    int end = start + C; if (end > NN) end = NN;
    int sum = 0;
    for (int i = start; i < end; i++) sum += g_cnt[i];
    s[t] = sum;
    __syncthreads();
    for (int d = 1; d < 1024; d <<= 1) {
        int v = (t >= d) ? s[t - d] : 0;
        __syncthreads();
        if (t >= d) s[t] += v;
        __syncthreads();
    }
    int run = (t == 0) ? 0 : s[t - 1];
    for (int i = start; i < end; i++) {
        g_off[i] = run; g_cur[i] = run; run += g_cnt[i];
    }
    if (t == 1023) g_off[NN] = run;
}

__global__ void k_fill(const int* __restrict__ ei) {
    int e = blockIdx.x * blockDim.x + threadIdx.x;
    if (e < NE) {
        int c = ei[NE + e];
        int r = ei[e];
        if ((unsigned)c >= (unsigned)NN || (unsigned)r >= (unsigned)NN) return;
        int p = atomicAdd(&g_cur[c], 1);
        g_src[p] = r;
        g_eid[p] = e;
    }
}

// ---------------- edge MLP: ew[p,:] = relu(W2 @ relu(W1 @ attr)) ----------------
// 64 threads/block = one edge at a time; W1/W2 rows held in registers,
// h1 exchanged via smem (broadcast reads -> cheap on crossbar).
__global__ void __launch_bounds__(64) k_ew(const float* __restrict__ ea,
                                           const float* __restrict__ W1,
                                           const float* __restrict__ W2) {
    int j = threadIdx.x;
    float w2r[64];
#pragma unroll
    for (int k = 0; k < 64; k += 4) {
        float4 v = *(const float4*)&W2[j * 64 + k];
        w2r[k] = v.x; w2r[k + 1] = v.y; w2r[k + 2] = v.z; w2r[k + 3] = v.w;
    }
    float w1r[8];
    {
        float4 v0 = *(const float4*)&W1[j * 8];
        float4 v1 = *(const float4*)&W1[j * 8 + 4];
        w1r[0] = v0.x; w1r[1] = v0.y; w1r[2] = v0.z; w1r[3] = v0.w;
        w1r[4] = v1.x; w1r[5] = v1.y; w1r[6] = v1.z; w1r[7] = v1.w;
    }
    __shared__ float h1s[64];
    for (int p = blockIdx.x; p < NE; p += gridDim.x) {
        int e = g_eid[p];
        float4 a0 = *(const float4*)&ea[(size_t)e * 8];
        float4 a1 = *(const float4*)&ea[(size_t)e * 8 + 4];
        float h1 = a0.x * w1r[0] + a0.y * w1r[1] + a0.z * w1r[2] + a0.w * w1r[3]
                 + a1.x * w1r[4] + a1.y * w1r[5] + a1.z * w1r[6] + a1.w * w1r[7];
        h1 = h1 > 0.f ? h1 : 0.f;
        __syncthreads();           // prior iteration's reads of h1s are done
        h1s[j] = h1;
        __syncthreads();
        float acc0 = 0.f, acc1 = 0.f, acc2 = 0.f, acc3 = 0.f;
#pragma unroll
        for (int k = 0; k < 64; k += 4) {
            float4 hv = *(const float4*)&h1s[k];
            acc0 = fmaf(hv.x, w2r[k],     acc0);
            acc1 = fmaf(hv.y, w2r[k + 1], acc1);
            acc2 = fmaf(hv.z, w2r[k + 2], acc2);
            acc3 = fmaf(hv.w, w2r[k + 3], acc3);
        }
        float r = (acc0 + acc1) + (acc2 + acc3);
        g_ew[(size_t)p * H + j] = r > 0.f ? r : 0.f;
    }
}

// ---------------- degree / dinv ----------------
__global__ void k_deg() {
    int n = blockIdx.x, j = threadIdx.x;
    int s = g_off[n], e = g_off[n + 1];
    float d = 1.f;                           // self-loop weight
    for (int p = s; p < e; p++) d += g_ew[(size_t)p * H + j];
    g_dinv[n * H + j] = rsqrtf(d);
}

// ---------------- per-layer pre: y = dinv * relu(h) * w_conv[l] ----------------
__global__ void k_pre(const float* __restrict__ wc, int first) {
    int i = blockIdx.x * blockDim.x + threadIdx.x;
    if (i >= NN * H) return;
    float v = first ? g_xlin[i] : g_h[i];
    v = v > 0.f ? v : 0.f;
    g_y[i] = g_dinv[i] * v * wc[i & 63];
}

// ---------------- aggregation: hagg = dinv*(sum ew*y[src] + y[n]) + b_conv ----------------
__global__ void k_agg(const float* __restrict__ bc) {
    int n = blockIdx.x, j = threadIdx.x;
    int s = g_off[n], e = g_off[n + 1];
    float acc = g_y[n * H + j];              // self loop: dinv^2 * xw == dinv * y[n]
    for (int p = s; p < e; p++) {
        int src = g_src[p];
        acc = fmaf(g_ew[(size_t)p * H + j], g_y[src * H + j], acc);
    }
    g_hagg[n * H + j] = fmaf(g_dinv[n * H + j], acc, bc[j]);
}

// ---------------- tiled SGEMM: C[N,64] = A[N,128] @ W[64,128]^T (+bias)(+resid) ----------------
// mode 0: A = xin (lda 128), bias = bi,  C = g_xlin
// mode 1: A = [g_xlin | g_hagg],         C = g_h, resid = g_xlin
__global__ void __launch_bounds__(256) k_gemm(const float* __restrict__ xin,
                                              const float* __restrict__ W,
                                              const float* __restrict__ bias,
                                              int mode) {
    __shared__ float As[16][68];
    __shared__ float Bs[16][68];
    const float *A0, *A1, *resid; float* C; int lda;
    if (mode == 0) { A0 = xin;    A1 = xin + 64; lda = 128; resid = 0;      C = g_xlin; }
    else           { A0 = g_xlin; A1 = g_hagg;   lda = 64;  resid = g_xlin; C = g_h;    }
    int t = threadIdx.x;
    int tx = t & 15, ty = t >> 4;
    int bm = blockIdx.x * 64;
    float acc[4][4] = {};
    int lr = t >> 2, lc = (t & 3) * 4;   // A-tile load coords
    int bn = t & 63, bk = (t >> 6) * 4;  // B-tile load coords
    for (int kk = 0; kk < 128; kk += 16) {
        int m = bm + lr;
        float4 av = make_float4(0.f, 0.f, 0.f, 0.f);
        int kc = kk + lc;
        if (m < NN) {
            av = (kc < 64) ? *(const float4*)&A0[(size_t)m * lda + kc]
                           : *(const float4*)&A1[(size_t)m * lda + kc - 64];
        }
        As[lc + 0][lr] = av.x; As[lc + 1][lr] = av.y;
        As[lc + 2][lr] = av.z; As[lc + 3][lr] = av.w;
        float4 bv = *(const float4*)&W[bn * 128 + kk + bk];
        Bs[bk + 0][bn] = bv.x; Bs[bk + 1][bn] = bv.y;
        Bs[bk + 2][bn] = bv.z; Bs[bk + 3][bn] = bv.w;
        __syncthreads();
#pragma unroll
        for (int k = 0; k < 16; k++) {
            float4 a = *(const float4*)&As[k][tx * 4];
            float4 b = *(const float4*)&Bs[k][ty * 4];
            acc[0][0] = fmaf(a.x, b.x, acc[0][0]); acc[0][1] = fmaf(a.x, b.y, acc[0][1]);
            acc[0][2] = fmaf(a.x, b.z, acc[0][2]); acc[0][3] = fmaf(a.x, b.w, acc[0][3]);
            acc[1][0] = fmaf(a.y, b.x, acc[1][0]); acc[1][1] = fmaf(a.y, b.y, acc[1][1]);
            acc[1][2] = fmaf(a.y, b.z, acc[1][2]); acc[1][3] = fmaf(a.y, b.w, acc[1][3]);
            acc[2][0] = fmaf(a.z, b.x, acc[2][0]); acc[2][1] = fmaf(a.z, b.y, acc[2][1]);
            acc[2][2] = fmaf(a.z, b.z, acc[2][2]); acc[2][3] = fmaf(a.z, b.w, acc[2][3]);
            acc[3][0] = fmaf(a.w, b.x, acc[3][0]); acc[3][1] = fmaf(a.w, b.y, acc[3][1]);
            acc[3][2] = fmaf(a.w, b.z, acc[3][2]); acc[3][3] = fmaf(a.w, b.w, acc[3][3]);
        }
        __syncthreads();
    }
#pragma unroll
    for (int i = 0; i < 4; i++) {
        int m = bm + tx * 4 + i;
        if (m >= NN) continue;
#pragma unroll
        for (int jj = 0; jj < 4; jj++) {
            int n = ty * 4 + jj;
            float v = acc[i][jj];
            if (bias)  v += bias[n];
            if (resid) v += resid[m * 64 + n];
            C[(size_t)m * 64 + n] = v;
        }
    }
}

// ---------------- output: out[n] = [x_ | relu(h)] . Wo ----------------
__global__ void k_out(const float* __restrict__ Wo, float* __restrict__ out) {
    int gw = (blockIdx.x * blockDim.x + threadIdx.x) >> 5;
    int lane = threadIdx.x & 31;
    if (gw >= NN) return;
    const float* xr = &g_xlin[gw * 64];
    const float* hr = &g_h[gw * 64];
    float a = xr[lane] * Wo[lane] + xr[lane + 32] * Wo[lane + 32];
    float h0 = hr[lane];      h0 = h0 > 0.f ? h0 : 0.f;
    float h1 = hr[lane + 32]; h1 = h1 > 0.f ? h1 : 0.f;
    a += h0 * Wo[64 + lane] + h1 * Wo[96 + lane];
#pragma unroll
    for (int o = 16; o; o >>= 1) a += __shfl_down_sync(0xffffffffu, a, o);
    if (lane == 0) out[gw] = a;
}

// ---------------- host ----------------
extern "C" void kernel_launch(void* const* d_in, const int* in_sizes, int n_in,
                              void* d_out, int out_size) {
    const float* x  = (const float*)d_in[0];
    const int*   ei = (const int*)d_in[1];     // int32 [2, E] (harness dtype set)
    const float* ea = (const float*)d_in[2];
    const float* W1 = (const float*)d_in[3];
    const float* W2 = (const float*)d_in[4];
    const float* Wi = (const float*)d_in[5];
    const float* bi = (const float*)d_in[6];
    const float* wc = (const float*)d_in[7];
    const float* bc = (const float*)d_in[8];
    const float* Wl = (const float*)d_in[9];
    const float* Wo = (const float*)d_in[10];
    float* out = (float*)d_out;

    k_zero<<<(NN + 1023) / 1024, 1024>>>();
    k_count<<<(NE + 255) / 256, 256>>>(ei);
    k_scan<<<1, 1024>>>();
    k_fill<<<(NE + 255) / 256, 256>>>(ei);
    k_ew<<<1664, 64>>>(ea, W1, W2);
    k_deg<<<NN, 64>>>();
    k_gemm<<<(NN + 63) / 64, 256>>>(x, Wi, bi, 0);
    for (int l = 0; l < 3; l++) {
        k_pre<<<(NN * H + 255) / 256, 256>>>(wc + l * 64, l == 0 ? 1 : 0);
        k_agg<<<NN, 64>>>(bc + l * 64);
        k_gemm<<<(NN + 63) / 64, 256>>>(x, Wl + l * 64 * 128, nullptr, 1);
    }
    k_out<<<(NN + 7) / 8, 256>>>(Wo, out);
}

// round 3
// speedup vs baseline: 1.4718x; 1.4718x over previous
#include <cuda_runtime.h>
#include <cuda_fp16.h>

#define NN 100000
#define NE 1600000
#define H  64

// ---------------- scratch (device globals; no allocation) ----------------
__device__ __half g_ew[1600000ull * 64];  // edge weights fp16, CSR-slot order [E,64]
__device__ int    g_cnt[NN];
__device__ int    g_off[NN + 1];
__device__ int    g_cur[NN];
__device__ int    g_src[NE];
__device__ int    g_eid[NE];
__device__ float  g_xlin[NN * H];
__device__ float  g_dinv[NN * H];
__device__ float  g_y[NN * H];
__device__ float  g_hagg[NN * H];
__device__ float  g_h[NN * H];

// ---------------- CSR build ----------------
__global__ void k_zero() {
    int i = blockIdx.x * blockDim.x + threadIdx.x;
    if (i < NN) g_cnt[i] = 0;
}

__global__ void k_count(const int* __restrict__ ei) {
    int e = blockIdx.x * blockDim.x + threadIdx.x;
    if (e < NE) {
        int c = ei[NE + e];
        if ((unsigned)c < (unsigned)NN) atomicAdd(&g_cnt[c], 1);
    }
}

__global__ void k_scan() {
    __shared__ int s[1024];
    int t = threadIdx.x;
    const int C = (NN + 1023) / 1024;
    int start = t * C; if (start > NN) start = NN;
    int end = start + C; if (end > NN) end = NN;
    int sum = 0;
    for (int i = start; i < end; i++) sum += g_cnt[i];
    s[t] = sum;
    __syncthreads();
    for (int d = 1; d < 1024; d <<= 1) {
        int v = (t >= d) ? s[t - d] : 0;
        __syncthreads();
        if (t >= d) s[t] += v;
        __syncthreads();
    }
    int run = (t == 0) ? 0 : s[t - 1];
    for (int i = start; i < end; i++) {
        g_off[i] = run; g_cur[i] = run; run += g_cnt[i];
    }
    if (t == 1023) g_off[NN] = run;
}

__global__ void k_fill(const int* __restrict__ ei) {
    int e = blockIdx.x * blockDim.x + threadIdx.x;
    if (e < NE) {
        int c = ei[NE + e];
        int r = ei[e];
        if ((unsigned)c >= (unsigned)NN || (unsigned)r >= (unsigned)NN) return;
        int p = atomicAdd(&g_cur[c], 1);
        g_src[p] = r;
        g_eid[p] = e;
    }
}

// ---------------- edge MLP: ew[p,:] = relu(W2 @ relu(W1 @ attr)), 8 edges/round ----------------
__global__ void __launch_bounds__(64) k_ew(const float* __restrict__ ea,
                                           const float* __restrict__ W1,
                                           const float* __restrict__ W2) {
    int j = threadIdx.x;
    float w2r[64];
#pragma unroll
    for (int k = 0; k < 64; k += 4) {
        float4 v = *(const float4*)&W2[j * 64 + k];
        w2r[k] = v.x; w2r[k + 1] = v.y; w2r[k + 2] = v.z; w2r[k + 3] = v.w;
    }
    float w1r[8];
    {
        float4 v0 = *(const float4*)&W1[j * 8];
        float4 v1 = *(const float4*)&W1[j * 8 + 4];
        w1r[0] = v0.x; w1r[1] = v0.y; w1r[2] = v0.z; w1r[3] = v0.w;
        w1r[4] = v1.x; w1r[5] = v1.y; w1r[6] = v1.z; w1r[7] = v1.w;
    }
    __shared__ float attrs[8][8];
    __shared__ float h1s[8][64];
    for (int p = blockIdx.x * 8; p < NE; p += gridDim.x * 8) {
        __syncthreads();                       // prior round's smem reads done
        {
            int e = g_eid[p + (j >> 3)];
            attrs[j >> 3][j & 7] = ea[(size_t)e * 8 + (j & 7)];
        }
        __syncthreads();
#pragma unroll
        for (int t = 0; t < 8; t++) {
            float4 a0 = *(const float4*)&attrs[t][0];
            float4 a1 = *(const float4*)&attrs[t][4];
            float v = a0.x * w1r[0] + a0.y * w1r[1] + a0.z * w1r[2] + a0.w * w1r[3]
                    + a1.x * w1r[4] + a1.y * w1r[5] + a1.z * w1r[6] + a1.w * w1r[7];
            h1s[t][j] = v > 0.f ? v : 0.f;
        }
        __syncthreads();
        float acc[8] = {};
#pragma unroll
        for (int k = 0; k < 64; k += 4) {
#pragma unroll
            for (int t = 0; t < 8; t++) {
                float4 hv = *(const float4*)&h1s[t][k];
                acc[t] = fmaf(hv.x, w2r[k],     acc[t]);
                acc[t] = fmaf(hv.y, w2r[k + 1], acc[t]);
                acc[t] = fmaf(hv.z, w2r[k + 2], acc[t]);
                acc[t] = fmaf(hv.w, w2r[k + 3], acc[t]);
            }
        }
#pragma unroll
        for (int t = 0; t < 8; t++) {
            float r = acc[t] > 0.f ? acc[t] : 0.f;
            g_ew[(size_t)(p + t) * 64 + j] = __float2half(r);
        }
    }
}

// ---------------- degree / dinv (warp per node, half2) ----------------
__global__ void __launch_bounds__(256) k_deg() {
    int w = (blockIdx.x * blockDim.x + threadIdx.x) >> 5;
    int lane = threadIdx.x & 31;
    if (w >= NN) return;
    int s = g_off[w], e = g_off[w + 1];
    const __half2* ewv = (const __half2*)g_ew;
    float dx = 1.f, dy = 1.f;                 // self-loop weight
    for (int p = s; p < e; p++) {
        float2 v = __half22float2(ewv[(size_t)p * 32 + lane]);
        dx += v.x; dy += v.y;
    }
    float2 r; r.x = rsqrtf(dx); r.y = rsqrtf(dy);
    ((float2*)g_dinv)[(size_t)w * 32 + lane] = r;
}

// ---------------- aggregation (warp per node): hagg = dinv*(sum ew*y[src] + y[n]) + bc ----------------
__global__ void __launch_bounds__(256) k_agg(const float* __restrict__ bc) {
    int w = (blockIdx.x * blockDim.x + threadIdx.x) >> 5;
    int lane = threadIdx.x & 31;
    if (w >= NN) return;
    int s = g_off[w], e = g_off[w + 1];
    const float2*  yv  = (const float2*)g_y;
    const __half2* ewv = (const __half2*)g_ew;
    float2 a0 = yv[(size_t)w * 32 + lane];    // self loop: dinv^2*xw == dinv*y[n]
    float2 a1 = make_float2(0.f, 0.f);
    int p = s;
    for (; p + 2 <= e; p += 2) {
        int s0 = g_src[p], s1 = g_src[p + 1];
        __half2 h0 = ewv[(size_t)p * 32 + lane];
        __half2 h1 = ewv[(size_t)(p + 1) * 32 + lane];
        float2 y0 = yv[(size_t)s0 * 32 + lane];
        float2 y1 = yv[(size_t)s1 * 32 + lane];
        float2 f0 = __half22float2(h0), f1 = __half22float2(h1);
        a0.x = fmaf(f0.x, y0.x, a0.x); a0.y = fmaf(f0.y, y0.y, a0.y);
        a1.x = fmaf(f1.x, y1.x, a1.x); a1.y = fmaf(f1.y, y1.y, a1.y);
    }
    if (p < e) {
        int s0 = g_src[p];
        float2 f0 = __half22float2(ewv[(size_t)p * 32 + lane]);
        float2 y0 = yv[(size_t)s0 * 32 + lane];
        a0.x = fmaf(f0.x, y0.x, a0.x); a0.y = fmaf(f0.y, y0.y, a0.y);
    }
    float2 dv = ((const float2*)g_dinv)[(size_t)w * 32 + lane];
    float2 r;
    r.x = fmaf(dv.x, a0.x + a1.x, bc[2 * lane]);
    r.y = fmaf(dv.y, a0.y + a1.y, bc[2 * lane + 1]);
    ((float2*)g_hagg)[(size_t)w * 32 + lane] = r;
}

// ---------------- tiled SGEMM: C[N,64] = A[N,128] @ W[64,128]^T (+bias)(+resid)(+y epilogue) ----
// mode 0: A = xin (lda 128), bias = bi,  C = g_xlin
// mode 1: A = [g_xlin | g_hagg],         C = g_h, resid = g_xlin
// if ywc != null: g_y = g_dinv * relu(C) * ywc[ch]   (fused k_pre for the NEXT agg)
__global__ void __launch_bounds__(256) k_gemm(const float* __restrict__ xin,
                                              const float* __restrict__ W,
                                              const float* __restrict__ bias,
                                              int mode,
                                              const float* __restrict__ ywc) {
    __shared__ float As[16][68];
    __shared__ float Bs[16][68];
    const float *A0, *A1, *resid; float* C; int lda;
    if (mode == 0) { A0 = xin;    A1 = xin + 64; lda = 128; resid = 0;      C = g_xlin; }
    else           { A0 = g_xlin; A1 = g_hagg;   lda = 64;  resid = g_xlin; C = g_h;    }
    int t = threadIdx.x;
    int tx = t & 15, ty = t >> 4;
    int bm = blockIdx.x * 64;
    float acc[4][4] = {};
    int lr = t >> 2, lc = (t & 3) * 4;
    int bn = t & 63, bk = (t >> 6) * 4;
    for (int kk = 0; kk < 128; kk += 16) {
        int m = bm + lr;
        float4 av = make_float4(0.f, 0.f, 0.f, 0.f);
        int kc = kk + lc;
        if (m < NN) {
            av = (kc < 64) ? *(const float4*)&A0[(size_t)m * lda + kc]
                           : *(const float4*)&A1[(size_t)m * lda + kc - 64];
        }
        As[lc + 0][lr] = av.x; As[lc + 1][lr] = av.y;
        As[lc + 2][lr] = av.z; As[lc + 3][lr] = av.w;
        float4 bv = *(const float4*)&W[bn * 128 + kk + bk];
        Bs[bk + 0][bn] = bv.x; Bs[bk + 1][bn] = bv.y;
        Bs[bk + 2][bn] = bv.z; Bs[bk + 3][bn] = bv.w;
        __syncthreads();
#pragma unroll
        for (int k = 0; k < 16; k++) {
            float4 a = *(const float4*)&As[k][tx * 4];
            float4 b = *(const float4*)&Bs[k][ty * 4];
            acc[0][0] = fmaf(a.x, b.x, acc[0][0]); acc[0][1] = fmaf(a.x, b.y, acc[0][1]);
            acc[0][2] = fmaf(a.x, b.z, acc[0][2]); acc[0][3] = fmaf(a.x, b.w, acc[0][3]);
            acc[1][0] = fmaf(a.y, b.x, acc[1][0]); acc[1][1] = fmaf(a.y, b.y, acc[1][1]);
            acc[1][2] = fmaf(a.y, b.z, acc[1][2]); acc[1][3] = fmaf(a.y, b.w, acc[1][3]);
            acc[2][0] = fmaf(a.z, b.x, acc[2][0]); acc[2][1] = fmaf(a.z, b.y, acc[2][1]);
            acc[2][2] = fmaf(a.z, b.z, acc[2][2]); acc[2][3] = fmaf(a.z, b.w, acc[2][3]);
            acc[3][0] = fmaf(a.w, b.x, acc[3][0]); acc[3][1] = fmaf(a.w, b.y, acc[3][1]);
            acc[3][2] = fmaf(a.w, b.z, acc[3][2]); acc[3][3] = fmaf(a.w, b.w, acc[3][3]);
        }
        __syncthreads();
    }
#pragma unroll
    for (int i = 0; i < 4; i++) {
        int m = bm + tx * 4 + i;
        if (m >= NN) continue;
#pragma unroll
        for (int jj = 0; jj < 4; jj++) {
            int n = ty * 4 + jj;
            float v = acc[i][jj];
            if (bias)  v += bias[n];
            if (resid) v += resid[m * 64 + n];
            C[(size_t)m * 64 + n] = v;
            if (ywc) {
                float rv = v > 0.f ? v : 0.f;
                g_y[(size_t)m * 64 + n] = g_dinv[(size_t)m * 64 + n] * rv * ywc[n];
            }
        }
    }
}

// ---------------- output: out[n] = [x_ | relu(h)] . Wo ----------------
__global__ void k_out(const float* __restrict__ Wo, float* __restrict__ out) {
    int gw = (blockIdx.x * blockDim.x + threadIdx.x) >> 5;
    int lane = threadIdx.x & 31;
    if (gw >= NN) return;
    const float* xr = &g_xlin[gw * 64];
    const float* hr = &g_h[gw * 64];
    float a = xr[lane] * Wo[lane] + xr[lane + 32] * Wo[lane + 32];
    float h0 = hr[lane];      h0 = h0 > 0.f ? h0 : 0.f;
    float h1 = hr[lane + 32]; h1 = h1 > 0.f ? h1 : 0.f;
    a += h0 * Wo[64 + lane] + h1 * Wo[96 + lane];
#pragma unroll
    for (int o = 16; o; o >>= 1) a += __shfl_down_sync(0xffffffffu, a, o);
    if (lane == 0) out[gw] = a;
}

// ---------------- host ----------------
extern "C" void kernel_launch(void* const* d_in, const int* in_sizes, int n_in,
                              void* d_out, int out_size) {
    const float* x  = (const float*)d_in[0];
    const int*   ei = (const int*)d_in[1];     // int32 [2, E]
    const float* ea = (const float*)d_in[2];
    const float* W1 = (const float*)d_in[3];
    const float* W2 = (const float*)d_in[4];
    const float* Wi = (const float*)d_in[5];
    const float* bi = (const float*)d_in[6];
    const float* wc = (const float*)d_in[7];
    const float* bc = (const float*)d_in[8];
    const float* Wl = (const float*)d_in[9];
    const float* Wo = (const float*)d_in[10];
    float* out = (float*)d_out;

    const int WPB = 8;  // warps (nodes) per 256-thread block
    k_zero<<<(NN + 1023) / 1024, 1024>>>();
    k_count<<<(NE + 255) / 256, 256>>>(ei);
    k_scan<<<1, 1024>>>();
    k_fill<<<(NE + 255) / 256, 256>>>(ei);
    k_ew<<<2048, 64>>>(ea, W1, W2);
    k_deg<<<(NN + WPB - 1) / WPB, 256>>>();
    k_gemm<<<(NN + 63) / 64, 256>>>(x, Wi, bi, 0, wc);                 // xlin + y(l=0)
    for (int l = 0; l < 3; l++) {
        k_agg<<<(NN + WPB - 1) / WPB, 256>>>(bc + l * 64);
        k_gemm<<<(NN + 63) / 64, 256>>>(x, Wl + l * 64 * 128, nullptr, 1,
                                        l < 2 ? wc + (l + 1) * 64 : nullptr);
    }
    k_out<<<(NN + 7) / 8, 256>>>(Wo, out);
}

// round 5
// speedup vs baseline: 2.0883x; 1.4188x over previous
#include <cuda_runtime.h>
#include <cuda_fp16.h>
#include <cstdint>

#define NN 100000
#define NE 1600000
#define H  64

// ---------------- scratch (device globals; no allocation) ----------------
__device__ __half g_ew[1600000ull * 64];  // edge weights fp16, CSR-slot order [E,64]
__device__ int    g_cnt[NN];
__device__ int    g_off[NN + 1];
__device__ int    g_cur[NN];
__device__ int    g_src[NE];
__device__ int    g_eid[NE];
__device__ float  g_xlin[NN * H];
__device__ float  g_dinv[NN * H];
__device__ float  g_y[NN * H];
__device__ float  g_hagg[NN * H];
__device__ float  g_h[NN * H];

// ---------------- CSR build ----------------
__global__ void k_zero() {
    int i = blockIdx.x * blockDim.x + threadIdx.x;
    if (i < NN) g_cnt[i] = 0;
}

__global__ void k_count(const int* __restrict__ ei) {
    int e = blockIdx.x * blockDim.x + threadIdx.x;
    if (e < NE) {
        int c = ei[NE + e];
        if ((unsigned)c < (unsigned)NN) atomicAdd(&g_cnt[c], 1);
    }
}

__global__ void k_scan() {
    __shared__ int s[1024];
    int t = threadIdx.x;
    const int C = (NN + 1023) / 1024;
    int start = t * C; if (start > NN) start = NN;
    int end = start + C; if (end > NN) end = NN;
    int sum = 0;
    for (int i = start; i < end; i++) sum += g_cnt[i];
    s[t] = sum;
    __syncthreads();
    for (int d = 1; d < 1024; d <<= 1) {
        int v = (t >= d) ? s[t - d] : 0;
        __syncthreads();
        if (t >= d) s[t] += v;
        __syncthreads();
    }
    int run = (t == 0) ? 0 : s[t - 1];
    for (int i = start; i < end; i++) {
        g_off[i] = run; g_cur[i] = run; run += g_cnt[i];
    }
    if (t == 1023) g_off[NN] = run;
}

__global__ void k_fill(const int* __restrict__ ei) {
    int e = blockIdx.x * blockDim.x + threadIdx.x;
    if (e < NE) {
        int c = ei[NE + e];
        int r = ei[e];
        if ((unsigned)c >= (unsigned)NN || (unsigned)r >= (unsigned)NN) return;
        int p = atomicAdd(&g_cur[c], 1);
        g_src[p] = r;
        g_eid[p] = e;
    }
}

// ---------------- edge MLP (tensor-core): ew = relu( relu(ea@W1^T) @ W2^T ) ----------------
// Block = 256 threads = 8 warps = 256 edges (NE/256 = 6250 blocks exactly).
// Stage 1: SIMT fp32 h1 = relu(ea@W1^T) -> fp16 smem [256][72] (72-pad: conflict-free mma loads).
// Stage 2: mma.sync.m16n8k16 f32.f16.f16: [256x64] = h1[256x64] @ W2^T, W2 fp16 in smem.
__device__ __forceinline__ void mma16816(float c[4], const uint32_t a[4],
                                         uint32_t b0, uint32_t b1) {
    asm volatile(
        "mma.sync.aligned.m16n8k16.row.col.f32.f16.f16.f32 "
        "{%0,%1,%2,%3}, {%4,%5,%6,%7}, {%8,%9}, {%0,%1,%2,%3};"
        : "+f"(c[0]), "+f"(c[1]), "+f"(c[2]), "+f"(c[3])
        : "r"(a[0]), "r"(a[1]), "r"(a[2]), "r"(a[3]), "r"(b0), "r"(b1));
}

__global__ void __launch_bounds__(256) k_ew(const float* __restrict__ ea,
                                            const float* __restrict__ W1,
                                            const float* __restrict__ W2) {
    __shared__ __half h1s[256][72];   // 36864 B
    __shared__ __half w2s[64][72];    // 9216 B  (row n, col k)
    __shared__ float  w1s[64][8];     // 2048 B
    int t = threadIdx.x;
    for (int i = t; i < 512; i += 256) ((float*)w1s)[i] = W1[i];
    for (int i = t; i < 4096; i += 256) w2s[i >> 6][i & 63] = __float2half(W2[i]);
    __syncthreads();

    // ---- stage 1: h1 for edge slot (base + t) ----
    int base = blockIdx.x * 256;
    int e = g_eid[base + t];
    float4 a0 = *(const float4*)&ea[(size_t)e * 8];
    float4 a1 = *(const float4*)&ea[(size_t)e * 8 + 4];
#pragma unroll
    for (int ch = 0; ch < 64; ch += 2) {
        float4 p0 = *(const float4*)&w1s[ch][0];
        float4 p1 = *(const float4*)&w1s[ch][4];
        float4 q0 = *(const float4*)&w1s[ch + 1][0];
        float4 q1 = *(const float4*)&w1s[ch + 1][4];
        float v0 = a0.x * p0.x + a0.y * p0.y + a0.z * p0.z + a0.w * p0.w
                 + a1.x * p1.x + a1.y * p1.y + a1.z * p1.z + a1.w * p1.w;
        float v1 = a0.x * q0.x + a0.y * q0.y + a0.z * q0.z + a0.w * q0.w
                 + a1.x * q1.x + a1.y * q1.y + a1.z * q1.z + a1.w * q1.w;
        v0 = v0 > 0.f ? v0 : 0.f;
        v1 = v1 > 0.f ? v1 : 0.f;
        *(__half2*)&h1s[t][ch] = __floats2half2_rn(v0, v1);
    }
    __syncthreads();

    // ---- stage 2: warp w computes rows [w*32, w*32+32) x all 64 cols ----
    int w = t >> 5, l = t & 31;
    float c[2][8][4];
#pragma unroll
    for (int mt = 0; mt < 2; mt++)
#pragma unroll
        for (int nt = 0; nt < 8; nt++)
#pragma unroll
            for (int r = 0; r < 4; r++) c[mt][nt][r] = 0.f;

#pragma unroll
    for (int kc = 0; kc < 4; kc++) {
        int k0 = kc * 16 + (l & 3) * 2;
        uint32_t a[2][4];
#pragma unroll
        for (int mt = 0; mt < 2; mt++) {
            int r = w * 32 + mt * 16 + (l >> 2);
            a[mt][0] = *(const uint32_t*)&h1s[r][k0];
            a[mt][1] = *(const uint32_t*)&h1s[r + 8][k0];
            a[mt][2] = *(const uint32_t*)&h1s[r][k0 + 8];
            a[mt][3] = *(const uint32_t*)&h1s[r + 8][k0 + 8];
        }
#pragma unroll
        for (int nt = 0; nt < 8; nt++) {
            int nr = nt * 8 + (l >> 2);
            uint32_t b0 = *(const uint32_t*)&w2s[nr][k0];
            uint32_t b1 = *(const uint32_t*)&w2s[nr][k0 + 8];
            mma16816(c[0][nt], a[0], b0, b1);
            mma16816(c[1][nt], a[1], b0, b1);
        }
    }

    // ---- epilogue: relu -> fp16 -> g_ew ----
#pragma unroll
    for (int mt = 0; mt < 2; mt++) {
        int m = w * 32 + mt * 16 + (l >> 2);
#pragma unroll
        for (int nt = 0; nt < 8; nt++) {
            int n = nt * 8 + (l & 3) * 2;
            float v0 = c[mt][nt][0], v1 = c[mt][nt][1];
            float v2 = c[mt][nt][2], v3 = c[mt][nt][3];
            v0 = v0 > 0.f ? v0 : 0.f; v1 = v1 > 0.f ? v1 : 0.f;
            v2 = v2 > 0.f ? v2 : 0.f; v3 = v3 > 0.f ? v3 : 0.f;
            *(__half2*)&g_ew[(size_t)(base + m) * 64 + n]     = __floats2half2_rn(v0, v1);
            *(__half2*)&g_ew[(size_t)(base + m + 8) * 64 + n] = __floats2half2_rn(v2, v3);
        }
    }
}

// ---------------- degree / dinv (warp per node, half2) ----------------
__global__ void __launch_bounds__(256) k_deg() {
    int w = (blockIdx.x * blockDim.x + threadIdx.x) >> 5;
    int lane = threadIdx.x & 31;
    if (w >= NN) return;
    int s = g_off[w], e = g_off[w + 1];
    const __half2* ewv = (const __half2*)g_ew;
    float dx = 1.f, dy = 1.f;                 // self-loop weight
    for (int p = s; p < e; p++) {
        float2 v = __half22float2(ewv[(size_t)p * 32 + lane]);
        dx += v.x; dy += v.y;
    }
    float2 r; r.x = rsqrtf(dx); r.y = rsqrtf(dy);
    ((float2*)g_dinv)[(size_t)w * 32 + lane] = r;
}

// ---------------- aggregation (warp per node): hagg = dinv*(sum ew*y[src] + y[n]) + bc ----------------
__global__ void __launch_bounds__(256) k_agg(const float* __restrict__ bc) {
    int w = (blockIdx.x * blockDim.x + threadIdx.x) >> 5;
    int lane = threadIdx.x & 31;
    if (w >= NN) return;
    int s = g_off[w], e = g_off[w + 1];
    const float2*  yv  = (const float2*)g_y;
    const __half2* ewv = (const __half2*)g_ew;
    float2 a0 = yv[(size_t)w * 32 + lane];    // self loop: dinv^2*xw == dinv*y[n]
    float2 a1 = make_float2(0.f, 0.f);
    int p = s;
    for (; p + 2 <= e; p += 2) {
        int s0 = g_src[p], s1 = g_src[p + 1];
        __half2 h0 = ewv[(size_t)p * 32 + lane];
        __half2 h1 = ewv[(size_t)(p + 1) * 32 + lane];
        float2 y0 = yv[(size_t)s0 * 32 + lane];
        float2 y1 = yv[(size_t)s1 * 32 + lane];
        float2 f0 = __half22float2(h0), f1 = __half22float2(h1);
        a0.x = fmaf(f0.x, y0.x, a0.x); a0.y = fmaf(f0.y, y0.y, a0.y);
        a1.x = fmaf(f1.x, y1.x, a1.x); a1.y = fmaf(f1.y, y1.y, a1.y);
    }
    if (p < e) {
        int s0 = g_src[p];
        float2 f0 = __half22float2(ewv[(size_t)p * 32 + lane]);
        float2 y0 = yv[(size_t)s0 * 32 + lane];
        a0.x = fmaf(f0.x, y0.x, a0.x); a0.y = fmaf(f0.y, y0.y, a0.y);
    }
    float2 dv = ((const float2*)g_dinv)[(size_t)w * 32 + lane];
    float2 r;
    r.x = fmaf(dv.x, a0.x + a1.x, bc[2 * lane]);
    r.y = fmaf(dv.y, a0.y + a1.y, bc[2 * lane + 1]);
    ((float2*)g_hagg)[(size_t)w * 32 + lane] = r;
}

// ---------------- tiled SGEMM: C[N,64] = A[N,128] @ W[64,128]^T (+bias)(+resid)(+y epilogue) ----
__global__ void __launch_bounds__(256) k_gemm(const float* __restrict__ xin,
                                              const float* __restrict__ W,
                                              const float* __restrict__ bias,
                                              int mode,
                                              const float* __restrict__ ywc) {
    __shared__ float As[16][68];
    __shared__ float Bs[16][68];
    const float *A0, *A1, *resid; float* C; int lda;
    if (mode == 0) { A0 = xin;    A1 = xin + 64; lda = 128; resid = 0;      C = g_xlin; }
    else           { A0 = g_xlin; A1 = g_hagg;   lda = 64;  resid = g_xlin; C = g_h;    }
    int t = threadIdx.x;
    int tx = t & 15, ty = t >> 4;
    int bm = blockIdx.x * 64;
    float acc[4][4] = {};
    int lr = t >> 2, lc = (t & 3) * 4;
    int bn = t & 63, bk = (t >> 6) * 4;
    for (int kk = 0; kk < 128; kk += 16) {
        int m = bm + lr;
        float4 av = make_float4(0.f, 0.f, 0.f, 0.f);
        int kc = kk + lc;
        if (m < NN) {
            av = (kc < 64) ? *(const float4*)&A0[(size_t)m * lda + kc]
                           : *(const float4*)&A1[(size_t)m * lda + kc - 64];
        }
        As[lc + 0][lr] = av.x; As[lc + 1][lr] = av.y;
        As[lc + 2][lr] = av.z; As[lc + 3][lr] = av.w;
        float4 bv = *(const float4*)&W[bn * 128 + kk + bk];
        Bs[bk + 0][bn] = bv.x; Bs[bk + 1][bn] = bv.y;
        Bs[bk + 2][bn] = bv.z; Bs[bk + 3][bn] = bv.w;
        __syncthreads();
#pragma unroll
        for (int k = 0; k < 16; k++) {
            float4 a = *(const float4*)&As[k][tx * 4];
            float4 b = *(const float4*)&Bs[k][ty * 4];
            acc[0][0] = fmaf(a.x, b.x, acc[0][0]); acc[0][1] = fmaf(a.x, b.y, acc[0][1]);
            acc[0][2] = fmaf(a.x, b.z, acc[0][2]); acc[0][3] = fmaf(a.x, b.w, acc[0][3]);
            acc[1][0] = fmaf(a.y, b.x, acc[1][0]); acc[1][1] = fmaf(a.y, b.y, acc[1][1]);
            acc[1][2] = fmaf(a.y, b.z, acc[1][2]); acc[1][3] = fmaf(a.y, b.w, acc[1][3]);
            acc[2][0] = fmaf(a.z, b.x, acc[2][0]); acc[2][1] = fmaf(a.z, b.y, acc[2][1]);
            acc[2][2] = fmaf(a.z, b.z, acc[2][2]); acc[2][3] = fmaf(a.z, b.w, acc[2][3]);
            acc[3][0] = fmaf(a.w, b.x, acc[3][0]); acc[3][1] = fmaf(a.w, b.y, acc[3][1]);
            acc[3][2] = fmaf(a.w, b.z, acc[3][2]); acc[3][3] = fmaf(a.w, b.w, acc[3][3]);
        }
        __syncthreads();
    }
#pragma unroll
    for (int i = 0; i < 4; i++) {
        int m = bm + tx * 4 + i;
        if (m >= NN) continue;
#pragma unroll
        for (int jj = 0; jj < 4; jj++) {
            int n = ty * 4 + jj;
            float v = acc[i][jj];
            if (bias)  v += bias[n];
            if (resid) v += resid[m * 64 + n];
            C[(size_t)m * 64 + n] = v;
            if (ywc) {
                float rv = v > 0.f ? v : 0.f;
                g_y[(size_t)m * 64 + n] = g_dinv[(size_t)m * 64 + n] * rv * ywc[n];
            }
        }
    }
}

// ---------------- output: out[n] = [x_ | relu(h)] . Wo ----------------
__global__ void k_out(const float* __restrict__ Wo, float* __restrict__ out) {
    int gw = (blockIdx.x * blockDim.x + threadIdx.x) >> 5;
    int lane = threadIdx.x & 31;
    if (gw >= NN) return;
    const float* xr = &g_xlin[gw * 64];
    const float* hr = &g_h[gw * 64];
    float a = xr[lane] * Wo[lane] + xr[lane + 32] * Wo[lane + 32];
    float h0 = hr[lane];      h0 = h0 > 0.f ? h0 : 0.f;
    float h1 = hr[lane + 32]; h1 = h1 > 0.f ? h1 : 0.f;
    a += h0 * Wo[64 + lane] + h1 * Wo[96 + lane];
#pragma unroll
    for (int o = 16; o; o >>= 1) a += __shfl_down_sync(0xffffffffu, a, o);
    if (lane == 0) out[gw] = a;
}

// ---------------- host ----------------
extern "C" void kernel_launch(void* const* d_in, const int* in_sizes, int n_in,
                              void* d_out, int out_size) {
    const float* x  = (const float*)d_in[0];
    const int*   ei = (const int*)d_in[1];     // int32 [2, E]
    const float* ea = (const float*)d_in[2];
    const float* W1 = (const float*)d_in[3];
    const float* W2 = (const float*)d_in[4];
    const float* Wi = (const float*)d_in[5];
    const float* bi = (const float*)d_in[6];
    const float* wc = (const float*)d_in[7];
    const float* bc = (const float*)d_in[8];
    const float* Wl = (const float*)d_in[9];
    const float* Wo = (const float*)d_in[10];
    float* out = (float*)d_out;

    const int WPB = 8;
    k_zero<<<(NN + 1023) / 1024, 1024>>>();
    k_count<<<(NE + 255) / 256, 256>>>(ei);
    k_scan<<<1, 1024>>>();
    k_fill<<<(NE + 255) / 256, 256>>>(ei);
    k_ew<<<NE / 256, 256>>>(ea, W1, W2);
    k_deg<<<(NN + WPB - 1) / WPB, 256>>>();
    k_gemm<<<(NN + 63) / 64, 256>>>(x, Wi, bi, 0, wc);                 // xlin + y(l=0)
    for (int l = 0; l < 3; l++) {
        k_agg<<<(NN + WPB - 1) / WPB, 256>>>(bc + l * 64);
        k_gemm<<<(NN + 63) / 64, 256>>>(x, Wl + l * 64 * 128, nullptr, 1,
                                        l < 2 ? wc + (l + 1) * 64 : nullptr);
    }
    k_out<<<(NN + 7) / 8, 256>>>(Wo, out);
}

// round 6
// speedup vs baseline: 2.5779x; 1.2344x over previous
#include <cuda_runtime.h>
#include <cuda_fp16.h>
#include <cstdint>

#define NN 100000
#define NE 1600000
#define H  64

// ---------------- scratch (device globals; no allocation) ----------------
__device__ __half g_ew[1600000ull * 64];  // edge weights fp16, CSR-slot order [E,64]
__device__ int    g_cnt[NN];
__device__ int    g_off[NN + 1];
__device__ int    g_cur[NN];
__device__ int    g_src[NE];
__device__ int    g_eid[NE];
__device__ float  g_xlin[NN * H];
__device__ float  g_dinv[NN * H];
__device__ float  g_y[NN * H];
__device__ float  g_hagg[NN * H];
__device__ float  g_h[NN * H];

// ---------------- CSR build ----------------
__global__ void k_zero() {
    int i = blockIdx.x * blockDim.x + threadIdx.x;
    if (i < NN) g_cnt[i] = 0;
}

__global__ void k_count(const int* __restrict__ ei) {
    int e = blockIdx.x * blockDim.x + threadIdx.x;
    if (e < NE) {
        int c = ei[NE + e];
        if ((unsigned)c < (unsigned)NN) atomicAdd(&g_cnt[c], 1);
    }
}

__global__ void k_scan() {
    __shared__ int s[1024];
    int t = threadIdx.x;
    const int C = (NN + 1023) / 1024;
    int start = t * C; if (start > NN) start = NN;
    int end = start + C; if (end > NN) end = NN;
    int sum = 0;
    for (int i = start; i < end; i++) sum += g_cnt[i];
    s[t] = sum;
    __syncthreads();
    for (int d = 1; d < 1024; d <<= 1) {
        int v = (t >= d) ? s[t - d] : 0;
        __syncthreads();
        if (t >= d) s[t] += v;
        __syncthreads();
    }
    int run = (t == 0) ? 0 : s[t - 1];
    for (int i = start; i < end; i++) {
        g_off[i] = run; g_cur[i] = run; run += g_cnt[i];
    }
    if (t == 1023) g_off[NN] = run;
}

__global__ void k_fill(const int* __restrict__ ei) {
    int e = blockIdx.x * blockDim.x + threadIdx.x;
    if (e < NE) {
        int c = ei[NE + e];
        int r = ei[e];
        if ((unsigned)c >= (unsigned)NN || (unsigned)r >= (unsigned)NN) return;
        int p = atomicAdd(&g_cur[c], 1);
        g_src[p] = r;
        g_eid[p] = e;
    }
}

// ---------------- mma.m16n8k16 f32 += f16 x f16 ----------------
__device__ __forceinline__ void mma16816(float c[4], const uint32_t a[4],
                                         uint32_t b0, uint32_t b1) {
    asm volatile(
        "mma.sync.aligned.m16n8k16.row.col.f32.f16.f16.f32 "
        "{%0,%1,%2,%3}, {%4,%5,%6,%7}, {%8,%9}, {%0,%1,%2,%3};"
        : "+f"(c[0]), "+f"(c[1]), "+f"(c[2]), "+f"(c[3])
        : "r"(a[0]), "r"(a[1]), "r"(a[2]), "r"(a[3]), "r"(b0), "r"(b1));
}

// ---------------- edge MLP (tensor-core): ew = relu( relu(ea@W1^T) @ W2^T ) ----------------
__global__ void __launch_bounds__(256) k_ew(const float* __restrict__ ea,
                                            const float* __restrict__ W1,
                                            const float* __restrict__ W2) {
    __shared__ __half h1s[256][72];
    __shared__ __half w2s[64][72];
    __shared__ float  w1s[64][8];
    int t = threadIdx.x;
    for (int i = t; i < 512; i += 256) ((float*)w1s)[i] = W1[i];
    for (int i = t; i < 4096; i += 256) w2s[i >> 6][i & 63] = __float2half(W2[i]);
    __syncthreads();

    int base = blockIdx.x * 256;
    int e = g_eid[base + t];
    float4 a0 = *(const float4*)&ea[(size_t)e * 8];
    float4 a1 = *(const float4*)&ea[(size_t)e * 8 + 4];
#pragma unroll
    for (int ch = 0; ch < 64; ch += 2) {
        float4 p0 = *(const float4*)&w1s[ch][0];
        float4 p1 = *(const float4*)&w1s[ch][4];
        float4 q0 = *(const float4*)&w1s[ch + 1][0];
        float4 q1 = *(const float4*)&w1s[ch + 1][4];
        float v0 = a0.x * p0.x + a0.y * p0.y + a0.z * p0.z + a0.w * p0.w
                 + a1.x * p1.x + a1.y * p1.y + a1.z * p1.z + a1.w * p1.w;
        float v1 = a0.x * q0.x + a0.y * q0.y + a0.z * q0.z + a0.w * q0.w
                 + a1.x * q1.x + a1.y * q1.y + a1.z * q1.z + a1.w * q1.w;
        v0 = v0 > 0.f ? v0 : 0.f;
        v1 = v1 > 0.f ? v1 : 0.f;
        *(__half2*)&h1s[t][ch] = __floats2half2_rn(v0, v1);
    }
    __syncthreads();

    int w = t >> 5, l = t & 31;
    float c[2][8][4];
#pragma unroll
    for (int mt = 0; mt < 2; mt++)
#pragma unroll
        for (int nt = 0; nt < 8; nt++)
#pragma unroll
            for (int r = 0; r < 4; r++) c[mt][nt][r] = 0.f;

#pragma unroll
    for (int kc = 0; kc < 4; kc++) {
        int k0 = kc * 16 + (l & 3) * 2;
        uint32_t a[2][4];
#pragma unroll
        for (int mt = 0; mt < 2; mt++) {
            int r = w * 32 + mt * 16 + (l >> 2);
            a[mt][0] = *(const uint32_t*)&h1s[r][k0];
            a[mt][1] = *(const uint32_t*)&h1s[r + 8][k0];
            a[mt][2] = *(const uint32_t*)&h1s[r][k0 + 8];
            a[mt][3] = *(const uint32_t*)&h1s[r + 8][k0 + 8];
        }
#pragma unroll
        for (int nt = 0; nt < 8; nt++) {
            int nr = nt * 8 + (l >> 2);
            uint32_t b0 = *(const uint32_t*)&w2s[nr][k0];
            uint32_t b1 = *(const uint32_t*)&w2s[nr][k0 + 8];
            mma16816(c[0][nt], a[0], b0, b1);
            mma16816(c[1][nt], a[1], b0, b1);
        }
    }

#pragma unroll
    for (int mt = 0; mt < 2; mt++) {
        int m = w * 32 + mt * 16 + (l >> 2);
#pragma unroll
        for (int nt = 0; nt < 8; nt++) {
            int n = nt * 8 + (l & 3) * 2;
            float v0 = c[mt][nt][0], v1 = c[mt][nt][1];
            float v2 = c[mt][nt][2], v3 = c[mt][nt][3];
            v0 = v0 > 0.f ? v0 : 0.f; v1 = v1 > 0.f ? v1 : 0.f;
            v2 = v2 > 0.f ? v2 : 0.f; v3 = v3 > 0.f ? v3 : 0.f;
            *(__half2*)&g_ew[(size_t)(base + m) * 64 + n]     = __floats2half2_rn(v0, v1);
            *(__half2*)&g_ew[(size_t)(base + m + 8) * 64 + n] = __floats2half2_rn(v2, v3);
        }
    }
}

// ---------------- degree / dinv (warp per node, half2) ----------------
__global__ void __launch_bounds__(256) k_deg() {
    int w = (blockIdx.x * blockDim.x + threadIdx.x) >> 5;
    int lane = threadIdx.x & 31;
    if (w >= NN) return;
    int s = g_off[w], e = g_off[w + 1];
    const __half2* ewv = (const __half2*)g_ew;
    float dx = 1.f, dy = 1.f;
    for (int p = s; p < e; p++) {
        float2 v = __half22float2(ewv[(size_t)p * 32 + lane]);
        dx += v.x; dy += v.y;
    }
    float2 r; r.x = rsqrtf(dx); r.y = rsqrtf(dy);
    ((float2*)g_dinv)[(size_t)w * 32 + lane] = r;
}

// ---------------- aggregation (warp per node), unroll 4 ----------------
__global__ void __launch_bounds__(256) k_agg(const float* __restrict__ bc) {
    int w = (blockIdx.x * blockDim.x + threadIdx.x) >> 5;
    int lane = threadIdx.x & 31;
    if (w >= NN) return;
    int s = g_off[w], e = g_off[w + 1];
    const float2*  yv  = (const float2*)g_y;
    const __half2* ewv = (const __half2*)g_ew;
    float2 a0 = yv[(size_t)w * 32 + lane];    // self loop
    float2 a1 = make_float2(0.f, 0.f);
    float2 a2 = make_float2(0.f, 0.f);
    float2 a3 = make_float2(0.f, 0.f);
    int p = s;
    for (; p + 4 <= e; p += 4) {
        int s0 = g_src[p], s1 = g_src[p + 1], s2 = g_src[p + 2], s3 = g_src[p + 3];
        __half2 h0 = ewv[(size_t)p * 32 + lane];
        __half2 h1 = ewv[(size_t)(p + 1) * 32 + lane];
        __half2 h2 = ewv[(size_t)(p + 2) * 32 + lane];
        __half2 h3 = ewv[(size_t)(p + 3) * 32 + lane];
        float2 y0 = yv[(size_t)s0 * 32 + lane];
        float2 y1 = yv[(size_t)s1 * 32 + lane];
        float2 y2 = yv[(size_t)s2 * 32 + lane];
        float2 y3 = yv[(size_t)s3 * 32 + lane];
        float2 f0 = __half22float2(h0), f1 = __half22float2(h1);
        float2 f2 = __half22float2(h2), f3 = __half22float2(h3);
        a0.x = fmaf(f0.x, y0.x, a0.x); a0.y = fmaf(f0.y, y0.y, a0.y);
        a1.x = fmaf(f1.x, y1.x, a1.x); a1.y = fmaf(f1.y, y1.y, a1.y);
        a2.x = fmaf(f2.x, y2.x, a2.x); a2.y = fmaf(f2.y, y2.y, a2.y);
        a3.x = fmaf(f3.x, y3.x, a3.x); a3.y = fmaf(f3.y, y3.y, a3.y);
    }
    for (; p < e; p++) {
        int s0 = g_src[p];
        float2 f0 = __half22float2(ewv[(size_t)p * 32 + lane]);
        float2 y0 = yv[(size_t)s0 * 32 + lane];
        a0.x = fmaf(f0.x, y0.x, a0.x); a0.y = fmaf(f0.y, y0.y, a0.y);
    }
    float2 dv = ((const float2*)g_dinv)[(size_t)w * 32 + lane];
    float2 r;
    r.x = fmaf(dv.x, (a0.x + a1.x) + (a2.x + a3.x), bc[2 * lane]);
    r.y = fmaf(dv.y, (a0.y + a1.y) + (a2.y + a3.y), bc[2 * lane + 1]);
    ((float2*)g_hagg)[(size_t)w * 32 + lane] = r;
}

// ---------------- tensor-core GEMM: C[N,64] = A[N,128] @ W[64,128]^T (+bias)(+resid)(+y) ----
// M-tile 128 rows, K processed as two 64-col passes (pass0=A0, pass1=A1).
// mode 0: A0 = xin cols 0-63, A1 = xin cols 64-127 (lda 128), bias=bi, C=g_xlin
// mode 1: A0 = g_xlin, A1 = g_hagg (lda 64), resid=g_xlin, C=g_h
__global__ void __launch_bounds__(256) k_gemm(const float* __restrict__ xin,
                                              const float* __restrict__ W,
                                              const float* __restrict__ bias,
                                              int mode,
                                              const float* __restrict__ ywc) {
    __shared__ __half As[128][72];    // 18432 B
    __shared__ __half Bs[64][136];    // 17408 B
    int t = threadIdx.x;
    for (int i = t; i < 8192; i += 256) Bs[i >> 7][i & 127] = __float2half(W[i]);

    const float *A0, *A1, *resid; float* C; int lda;
    if (mode == 0) { A0 = xin;    A1 = xin + 64; lda = 128; resid = 0;      C = g_xlin; }
    else           { A0 = g_xlin; A1 = g_hagg;   lda = 64;  resid = g_xlin; C = g_h;    }

    int bm = blockIdx.x * 128;
    int w = t >> 5, l = t & 31;
    float c[8][4];
#pragma unroll
    for (int nt = 0; nt < 8; nt++)
#pragma unroll
        for (int r = 0; r < 4; r++) c[nt][r] = 0.f;

    int lrow = t >> 1, lc0 = (t & 1) * 32;
    bool lvalid = (bm + lrow) < NN;

#pragma unroll
    for (int pass = 0; pass < 2; pass++) {
        const float* A = pass ? A1 : A0;
        __syncthreads();                     // pass1: prior mma reads of As done
        const float* srcp = &A[(size_t)(bm + lrow) * lda + lc0];
#pragma unroll
        for (int ch = 0; ch < 4; ch++) {
            float4 v0 = make_float4(0.f, 0.f, 0.f, 0.f), v1 = v0;
            if (lvalid) {
                v0 = *(const float4*)&srcp[ch * 8];
                v1 = *(const float4*)&srcp[ch * 8 + 4];
            }
            __half2 h0 = __floats2half2_rn(v0.x, v0.y);
            __half2 h1 = __floats2half2_rn(v0.z, v0.w);
            __half2 h2 = __floats2half2_rn(v1.x, v1.y);
            __half2 h3 = __floats2half2_rn(v1.z, v1.w);
            uint4 pk;
            pk.x = *(uint32_t*)&h0; pk.y = *(uint32_t*)&h1;
            pk.z = *(uint32_t*)&h2; pk.w = *(uint32_t*)&h3;
            *(uint4*)&As[lrow][lc0 + ch * 8] = pk;
        }
        __syncthreads();
#pragma unroll
        for (int kc = 0; kc < 4; kc++) {
            int k0 = kc * 16 + (l & 3) * 2;
            int row = w * 16 + (l >> 2);
            uint32_t a[4];
            a[0] = *(const uint32_t*)&As[row][k0];
            a[1] = *(const uint32_t*)&As[row + 8][k0];
            a[2] = *(const uint32_t*)&As[row][k0 + 8];
            a[3] = *(const uint32_t*)&As[row + 8][k0 + 8];
            int kb = pass * 64 + k0;
#pragma unroll
            for (int nt = 0; nt < 8; nt++) {
                int nr = nt * 8 + (l >> 2);
                uint32_t b0 = *(const uint32_t*)&Bs[nr][kb];
                uint32_t b1 = *(const uint32_t*)&Bs[nr][kb + 8];
                mma16816(c[nt], a, b0, b1);
            }
        }
    }

    // epilogue
    int m0 = bm + w * 16 + (l >> 2);
    int n0 = (l & 3) * 2;
#pragma unroll
    for (int nt = 0; nt < 8; nt++) {
        int n = nt * 8 + n0;
#pragma unroll
        for (int rr = 0; rr < 2; rr++) {
            int m = m0 + rr * 8;
            if (m >= NN) continue;
            float v0 = c[nt][rr * 2], v1 = c[nt][rr * 2 + 1];
            if (bias) { v0 += bias[n]; v1 += bias[n + 1]; }
            if (resid) {
                float2 rv = *(const float2*)&resid[(size_t)m * 64 + n];
                v0 += rv.x; v1 += rv.y;
            }
            float2 ov; ov.x = v0; ov.y = v1;
            *(float2*)&C[(size_t)m * 64 + n] = ov;
            if (ywc) {
                float2 dv = *(const float2*)&g_dinv[(size_t)m * 64 + n];
                float r0 = v0 > 0.f ? v0 : 0.f;
                float r1 = v1 > 0.f ? v1 : 0.f;
                float2 yo;
                yo.x = dv.x * r0 * ywc[n];
                yo.y = dv.y * r1 * ywc[n + 1];
                *(float2*)&g_y[(size_t)m * 64 + n] = yo;
            }
        }
    }
}

// ---------------- output: out[n] = [x_ | relu(h)] . Wo ----------------
__global__ void k_out(const float* __restrict__ Wo, float* __restrict__ out) {
    int gw = (blockIdx.x * blockDim.x + threadIdx.x) >> 5;
    int lane = threadIdx.x & 31;
    if (gw >= NN) return;
    const float* xr = &g_xlin[gw * 64];
    const float* hr = &g_h[gw * 64];
    float a = xr[lane] * Wo[lane] + xr[lane + 32] * Wo[lane + 32];
    float h0 = hr[lane];      h0 = h0 > 0.f ? h0 : 0.f;
    float h1 = hr[lane + 32]; h1 = h1 > 0.f ? h1 : 0.f;
    a += h0 * Wo[64 + lane] + h1 * Wo[96 + lane];
#pragma unroll
    for (int o = 16; o; o >>= 1) a += __shfl_down_sync(0xffffffffu, a, o);
    if (lane == 0) out[gw] = a;
}

// ---------------- host ----------------
extern "C" void kernel_launch(void* const* d_in, const int* in_sizes, int n_in,
                              void* d_out, int out_size) {
    const float* x  = (const float*)d_in[0];
    const int*   ei = (const int*)d_in[1];     // int32 [2, E]
    const float* ea = (const float*)d_in[2];
    const float* W1 = (const float*)d_in[3];
    const float* W2 = (const float*)d_in[4];
    const float* Wi = (const float*)d_in[5];
    const float* bi = (const float*)d_in[6];
    const float* wc = (const float*)d_in[7];
    const float* bc = (const float*)d_in[8];
    const float* Wl = (const float*)d_in[9];
    const float* Wo = (const float*)d_in[10];
    float* out = (float*)d_out;

    const int WPB = 8;
    k_zero<<<(NN + 1023) / 1024, 1024>>>();
    k_count<<<(NE + 255) / 256, 256>>>(ei);
    k_scan<<<1, 1024>>>();
    k_fill<<<(NE + 255) / 256, 256>>>(ei);
    k_ew<<<NE / 256, 256>>>(ea, W1, W2);
    k_deg<<<(NN + WPB - 1) / WPB, 256>>>();
    k_gemm<<<(NN + 127) / 128, 256>>>(x, Wi, bi, 0, wc);               // xlin + y(l=0)
    for (int l = 0; l < 3; l++) {
        k_agg<<<(NN + WPB - 1) / WPB, 256>>>(bc + l * 64);
        k_gemm<<<(NN + 127) / 128, 256>>>(x, Wl + l * 64 * 128, nullptr, 1,
                                          l < 2 ? wc + (l + 1) * 64 : nullptr);
    }
    k_out<<<(NN + 7) / 8, 256>>>(Wo, out);
}

// round 7
// speedup vs baseline: 2.7315x; 1.0596x over previous
#include <cuda_runtime.h>
#include <cuda_fp16.h>
#include <cstdint>

#define NN 100000
#define NE 1600000
#define H  64

// ---------------- scratch (device globals; no allocation) ----------------
__device__ __half g_ew[1600000ull * 64];  // edge weights fp16, CSR-slot order [E,64]
__device__ int    g_cnt[NN];
__device__ int    g_off[NN + 1];
__device__ int    g_cur[NN];
__device__ int    g_src[NE];              // CSR-slot -> source node
__device__ int    g_pos[NE];              // edge e -> CSR slot
__device__ float  g_xlin[NN * H];
__device__ float  g_dinv[NN * H];
__device__ float  g_y[NN * H];
__device__ float  g_hagg[NN * H];
__device__ float  g_h[NN * H];

// ---------------- CSR build ----------------
__global__ void k_zero() {
    int i = blockIdx.x * blockDim.x + threadIdx.x;
    if (i < NN) g_cnt[i] = 0;
}

__global__ void k_count(const int* __restrict__ ei) {
    int e = blockIdx.x * blockDim.x + threadIdx.x;
    if (e < NE) {
        int c = ei[NE + e];
        if ((unsigned)c < (unsigned)NN) atomicAdd(&g_cnt[c], 1);
    }
}

__global__ void k_scan() {
    __shared__ int s[1024];
    int t = threadIdx.x;
    const int C = (NN + 1023) / 1024;
    int start = t * C; if (start > NN) start = NN;
    int end = start + C; if (end > NN) end = NN;
    int sum = 0;
    for (int i = start; i < end; i++) sum += g_cnt[i];
    s[t] = sum;
    __syncthreads();
    for (int d = 1; d < 1024; d <<= 1) {
        int v = (t >= d) ? s[t - d] : 0;
        __syncthreads();
        if (t >= d) s[t] += v;
        __syncthreads();
    }
    int run = (t == 0) ? 0 : s[t - 1];
    for (int i = start; i < end; i++) {
        g_off[i] = run; g_cur[i] = run; run += g_cnt[i];
    }
    if (t == 1023) g_off[NN] = run;
}

__global__ void k_fill(const int* __restrict__ ei) {
    int e = blockIdx.x * blockDim.x + threadIdx.x;
    if (e < NE) {
        int c = ei[NE + e];
        int r = ei[e];
        if ((unsigned)c >= (unsigned)NN || (unsigned)r >= (unsigned)NN) return;
        int p = atomicAdd(&g_cur[c], 1);
        g_src[p] = r;          // scattered
        g_pos[e] = p;          // coalesced
    }
}

// ---------------- mma.m16n8k16 f32 += f16 x f16 ----------------
__device__ __forceinline__ void mma16816(float c[4], const uint32_t a[4],
                                         uint32_t b0, uint32_t b1) {
    asm volatile(
        "mma.sync.aligned.m16n8k16.row.col.f32.f16.f16.f32 "
        "{%0,%1,%2,%3}, {%4,%5,%6,%7}, {%8,%9}, {%0,%1,%2,%3};"
        : "+f"(c[0]), "+f"(c[1]), "+f"(c[2]), "+f"(c[3])
        : "r"(a[0]), "r"(a[1]), "r"(a[2]), "r"(a[3]), "r"(b0), "r"(b1));
}

// ---------------- edge MLP (tensor-core): ew = relu( relu(ea@W1^T) @ W2^T ) ----------------
// Edges processed in ORIGINAL order (coalesced ea); rows scatter-stored to CSR slots.
__global__ void __launch_bounds__(256) k_ew(const float* __restrict__ ea,
                                            const float* __restrict__ W1,
                                            const float* __restrict__ W2) {
    __shared__ __half h1s[256][72];
    __shared__ __half w2s[64][72];
    __shared__ float  w1s[64][8];
    __shared__ int    poss[256];
    int t = threadIdx.x;
    for (int i = t; i < 512; i += 256) ((float*)w1s)[i] = W1[i];
    for (int i = t; i < 4096; i += 256) w2s[i >> 6][i & 63] = __float2half(W2[i]);

    int base = blockIdx.x * 256;
    poss[t] = g_pos[base + t];
    float4 a0 = *(const float4*)&ea[(size_t)(base + t) * 8];
    float4 a1 = *(const float4*)&ea[(size_t)(base + t) * 8 + 4];
    __syncthreads();
#pragma unroll
    for (int ch = 0; ch < 64; ch += 2) {
        float4 p0 = *(const float4*)&w1s[ch][0];
        float4 p1 = *(const float4*)&w1s[ch][4];
        float4 q0 = *(const float4*)&w1s[ch + 1][0];
        float4 q1 = *(const float4*)&w1s[ch + 1][4];
        float v0 = a0.x * p0.x + a0.y * p0.y + a0.z * p0.z + a0.w * p0.w
                 + a1.x * p1.x + a1.y * p1.y + a1.z * p1.z + a1.w * p1.w;
        float v1 = a0.x * q0.x + a0.y * q0.y + a0.z * q0.z + a0.w * q0.w
                 + a1.x * q1.x + a1.y * q1.y + a1.z * q1.z + a1.w * q1.w;
        v0 = v0 > 0.f ? v0 : 0.f;
        v1 = v1 > 0.f ? v1 : 0.f;
        *(__half2*)&h1s[t][ch] = __floats2half2_rn(v0, v1);
    }
    __syncthreads();

    int w = t >> 5, l = t & 31;
    float c[2][8][4];
#pragma unroll
    for (int mt = 0; mt < 2; mt++)
#pragma unroll
        for (int nt = 0; nt < 8; nt++)
#pragma unroll
            for (int r = 0; r < 4; r++) c[mt][nt][r] = 0.f;

#pragma unroll
    for (int kc = 0; kc < 4; kc++) {
        int k0 = kc * 16 + (l & 3) * 2;
        uint32_t a[2][4];
#pragma unroll
        for (int mt = 0; mt < 2; mt++) {
            int r = w * 32 + mt * 16 + (l >> 2);
            a[mt][0] = *(const uint32_t*)&h1s[r][k0];
            a[mt][1] = *(const uint32_t*)&h1s[r + 8][k0];
            a[mt][2] = *(const uint32_t*)&h1s[r][k0 + 8];
            a[mt][3] = *(const uint32_t*)&h1s[r + 8][k0 + 8];
        }
#pragma unroll
        for (int nt = 0; nt < 8; nt++) {
            int nr = nt * 8 + (l >> 2);
            uint32_t b0 = *(const uint32_t*)&w2s[nr][k0];
            uint32_t b1 = *(const uint32_t*)&w2s[nr][k0 + 8];
            mma16816(c[0][nt], a[0], b0, b1);
            mma16816(c[1][nt], a[1], b0, b1);
        }
    }

    // epilogue: relu -> fp16 -> scatter row to CSR slot
#pragma unroll
    for (int mt = 0; mt < 2; mt++) {
        int m = w * 32 + mt * 16 + (l >> 2);
        size_t row0 = (size_t)poss[m] * 64;
        size_t row1 = (size_t)poss[m + 8] * 64;
#pragma unroll
        for (int nt = 0; nt < 8; nt++) {
            int n = nt * 8 + (l & 3) * 2;
            float v0 = c[mt][nt][0], v1 = c[mt][nt][1];
            float v2 = c[mt][nt][2], v3 = c[mt][nt][3];
            v0 = v0 > 0.f ? v0 : 0.f; v1 = v1 > 0.f ? v1 : 0.f;
            v2 = v2 > 0.f ? v2 : 0.f; v3 = v3 > 0.f ? v3 : 0.f;
            *(__half2*)&g_ew[row0 + n] = __floats2half2_rn(v0, v1);
            *(__half2*)&g_ew[row1 + n] = __floats2half2_rn(v2, v3);
        }
    }
}

// ---------------- degree / dinv (warp per node, half2) ----------------
__global__ void __launch_bounds__(256) k_deg() {
    int w = (blockIdx.x * blockDim.x + threadIdx.x) >> 5;
    int lane = threadIdx.x & 31;
    if (w >= NN) return;
    int s = g_off[w], e = g_off[w + 1];
    const __half2* ewv = (const __half2*)g_ew;
    float dx = 1.f, dy = 1.f;
    for (int p = s; p < e; p++) {
        float2 v = __half22float2(ewv[(size_t)p * 32 + lane]);
        dx += v.x; dy += v.y;
    }
    float2 r; r.x = rsqrtf(dx); r.y = rsqrtf(dy);
    ((float2*)g_dinv)[(size_t)w * 32 + lane] = r;
}

// ---------------- aggregation (warp per node), unroll 4 ----------------
__global__ void __launch_bounds__(256) k_agg(const float* __restrict__ bc) {
    int w = (blockIdx.x * blockDim.x + threadIdx.x) >> 5;
    int lane = threadIdx.x & 31;
    if (w >= NN) return;
    int s = g_off[w], e = g_off[w + 1];
    const float2*  yv  = (const float2*)g_y;
    const __half2* ewv = (const __half2*)g_ew;
    float2 a0 = yv[(size_t)w * 32 + lane];    // self loop
    float2 a1 = make_float2(0.f, 0.f);
    float2 a2 = make_float2(0.f, 0.f);
    float2 a3 = make_float2(0.f, 0.f);
    int p = s;
    for (; p + 4 <= e; p += 4) {
        int s0 = g_src[p], s1 = g_src[p + 1], s2 = g_src[p + 2], s3 = g_src[p + 3];
        __half2 h0 = ewv[(size_t)p * 32 + lane];
        __half2 h1 = ewv[(size_t)(p + 1) * 32 + lane];
        __half2 h2 = ewv[(size_t)(p + 2) * 32 + lane];
        __half2 h3 = ewv[(size_t)(p + 3) * 32 + lane];
        float2 y0 = yv[(size_t)s0 * 32 + lane];
        float2 y1 = yv[(size_t)s1 * 32 + lane];
        float2 y2 = yv[(size_t)s2 * 32 + lane];
        float2 y3 = yv[(size_t)s3 * 32 + lane];
        float2 f0 = __half22float2(h0), f1 = __half22float2(h1);
        float2 f2 = __half22float2(h2), f3 = __half22float2(h3);
        a0.x = fmaf(f0.x, y0.x, a0.x); a0.y = fmaf(f0.y, y0.y, a0.y);
        a1.x = fmaf(f1.x, y1.x, a1.x); a1.y = fmaf(f1.y, y1.y, a1.y);
        a2.x = fmaf(f2.x, y2.x, a2.x); a2.y = fmaf(f2.y, y2.y, a2.y);
        a3.x = fmaf(f3.x, y3.x, a3.x); a3.y = fmaf(f3.y, y3.y, a3.y);
    }
    for (; p < e; p++) {
        int s0 = g_src[p];
        float2 f0 = __half22float2(ewv[(size_t)p * 32 + lane]);
        float2 y0 = yv[(size_t)s0 * 32 + lane];
        a0.x = fmaf(f0.x, y0.x, a0.x); a0.y = fmaf(f0.y, y0.y, a0.y);
    }
    float2 dv = ((const float2*)g_dinv)[(size_t)w * 32 + lane];
    float2 r;
    r.x = fmaf(dv.x, (a0.x + a1.x) + (a2.x + a3.x), bc[2 * lane]);
    r.y = fmaf(dv.y, (a0.y + a1.y) + (a2.y + a3.y), bc[2 * lane + 1]);
    ((float2*)g_hagg)[(size_t)w * 32 + lane] = r;
}

// ---------------- tensor-core GEMM: C[N,64] = A[N,128] @ W[64,128]^T ----------------
// mode 0: A0 = xin cols 0-63, A1 = xin cols 64-127 (lda 128), bias=bi, C=g_xlin
// mode 1: A0 = g_xlin, A1 = g_hagg (lda 64), resid=g_xlin, C=g_h
// ywc != null: fused y = dinv*relu(C)*ywc.   Wo != null (last layer): fused output
// out[m] = sum_n resid[m,n]*Wo[n] + relu(C[m,n])*Wo[64+n]  (skips g_h entirely).
__global__ void __launch_bounds__(256) k_gemm(const float* __restrict__ xin,
                                              const float* __restrict__ W,
                                              const float* __restrict__ bias,
                                              int mode,
                                              const float* __restrict__ ywc,
                                              const float* __restrict__ Wo,
                                              float* __restrict__ out) {
    __shared__ __half As[128][72];
    __shared__ __half Bs[64][136];
    int t = threadIdx.x;
    for (int i = t; i < 8192; i += 256) Bs[i >> 7][i & 127] = __float2half(W[i]);

    const float *A0, *A1, *resid; float* C; int lda;
    if (mode == 0) { A0 = xin;    A1 = xin + 64; lda = 128; resid = 0;      C = g_xlin; }
    else           { A0 = g_xlin; A1 = g_hagg;   lda = 64;  resid = g_xlin; C = g_h;    }

    int bm = blockIdx.x * 128;
    int w = t >> 5, l = t & 31;
    float c[8][4];
#pragma unroll
    for (int nt = 0; nt < 8; nt++)
#pragma unroll
        for (int r = 0; r < 4; r++) c[nt][r] = 0.f;

    int lrow = t >> 1, lc0 = (t & 1) * 32;
    bool lvalid = (bm + lrow) < NN;

#pragma unroll
    for (int pass = 0; pass < 2; pass++) {
        const float* A = pass ? A1 : A0;
        __syncthreads();
        const float* srcp = &A[(size_t)(bm + lrow) * lda + lc0];
#pragma unroll
        for (int ch = 0; ch < 4; ch++) {
            float4 v0 = make_float4(0.f, 0.f, 0.f, 0.f), v1 = v0;
            if (lvalid) {
                v0 = *(const float4*)&srcp[ch * 8];
                v1 = *(const float4*)&srcp[ch * 8 + 4];
            }
            __half2 h0 = __floats2half2_rn(v0.x, v0.y);
            __half2 h1 = __floats2half2_rn(v0.z, v0.w);
            __half2 h2 = __floats2half2_rn(v1.x, v1.y);
            __half2 h3 = __floats2half2_rn(v1.z, v1.w);
            uint4 pk;
            pk.x = *(uint32_t*)&h0; pk.y = *(uint32_t*)&h1;
            pk.z = *(uint32_t*)&h2; pk.w = *(uint32_t*)&h3;
            *(uint4*)&As[lrow][lc0 + ch * 8] = pk;
        }
        __syncthreads();
#pragma unroll
        for (int kc = 0; kc < 4; kc++) {
            int k0 = kc * 16 + (l & 3) * 2;
            int row = w * 16 + (l >> 2);
            uint32_t a[4];
            a[0] = *(const uint32_t*)&As[row][k0];
            a[1] = *(const uint32_t*)&As[row + 8][k0];
            a[2] = *(const uint32_t*)&As[row][k0 + 8];
            a[3] = *(const uint32_t*)&As[row + 8][k0 + 8];
            int kb = pass * 64 + k0;
#pragma unroll
            for (int nt = 0; nt < 8; nt++) {
                int nr = nt * 8 + (l >> 2);
                uint32_t b0 = *(const uint32_t*)&Bs[nr][kb];
                uint32_t b1 = *(const uint32_t*)&Bs[nr][kb + 8];
                mma16816(c[nt], a, b0, b1);
            }
        }
    }

    int m0 = bm + w * 16 + (l >> 2);
    int n0 = (l & 3) * 2;

    if (Wo) {
        // fused output: acc[rr] = sum over this thread's 16 cols
        float oacc[2] = {0.f, 0.f};
#pragma unroll
        for (int nt = 0; nt < 8; nt++) {
            int n = nt * 8 + n0;
            float wx0 = Wo[n], wx1 = Wo[n + 1];
            float wh0 = Wo[64 + n], wh1 = Wo[64 + n + 1];
#pragma unroll
            for (int rr = 0; rr < 2; rr++) {
                int m = m0 + rr * 8;
                if (m >= NN) continue;
                float2 rv = *(const float2*)&resid[(size_t)m * 64 + n];
                float h0 = c[nt][rr * 2] + rv.x;
                float h1 = c[nt][rr * 2 + 1] + rv.y;
                h0 = h0 > 0.f ? h0 : 0.f;
                h1 = h1 > 0.f ? h1 : 0.f;
                oacc[rr] += rv.x * wx0 + rv.y * wx1 + h0 * wh0 + h1 * wh1;
            }
        }
        // reduce across the 4 lanes (l&3) owning the same rows
#pragma unroll
        for (int rr = 0; rr < 2; rr++) {
            oacc[rr] += __shfl_xor_sync(0xffffffffu, oacc[rr], 1);
            oacc[rr] += __shfl_xor_sync(0xffffffffu, oacc[rr], 2);
        }
        if ((l & 3) == 0) {
            if (m0 < NN)     out[m0]     = oacc[0];
            if (m0 + 8 < NN) out[m0 + 8] = oacc[1];
        }
        return;
    }

#pragma unroll
    for (int nt = 0; nt < 8; nt++) {
        int n = nt * 8 + n0;
#pragma unroll
        for (int rr = 0; rr < 2; rr++) {
            int m = m0 + rr * 8;
            if (m >= NN) continue;
            float v0 = c[nt][rr * 2], v1 = c[nt][rr * 2 + 1];
            if (bias) { v0 += bias[n]; v1 += bias[n + 1]; }
            if (resid) {
                float2 rv = *(const float2*)&resid[(size_t)m * 64 + n];
                v0 += rv.x; v1 += rv.y;
            }
            float2 ov; ov.x = v0; ov.y = v1;
            *(float2*)&C[(size_t)m * 64 + n] = ov;
            if (ywc) {
                float2 dv = *(const float2*)&g_dinv[(size_t)m * 64 + n];
                float r0 = v0 > 0.f ? v0 : 0.f;
                float r1 = v1 > 0.f ? v1 : 0.f;
                float2 yo;
                yo.x = dv.x * r0 * ywc[n];
                yo.y = dv.y * r1 * ywc[n + 1];
                *(float2*)&g_y[(size_t)m * 64 + n] = yo;
            }
        }
    }
}

// ---------------- host ----------------
extern "C" void kernel_launch(void* const* d_in, const int* in_sizes, int n_in,
                              void* d_out, int out_size) {
    const float* x  = (const float*)d_in[0];
    const int*   ei = (const int*)d_in[1];     // int32 [2, E]
    const float* ea = (const float*)d_in[2];
    const float* W1 = (const float*)d_in[3];
    const float* W2 = (const float*)d_in[4];
    const float* Wi = (const float*)d_in[5];
    const float* bi = (const float*)d_in[6];
    const float* wc = (const float*)d_in[7];
    const float* bc = (const float*)d_in[8];
    const float* Wl = (const float*)d_in[9];
    const float* Wo = (const float*)d_in[10];
    float* out = (float*)d_out;

    const int WPB = 8;
    k_zero<<<(NN + 1023) / 1024, 1024>>>();
    k_count<<<(NE + 255) / 256, 256>>>(ei);
    k_scan<<<1, 1024>>>();
    k_fill<<<(NE + 255) / 256, 256>>>(ei);
    k_ew<<<NE / 256, 256>>>(ea, W1, W2);
    k_deg<<<(NN + WPB - 1) / WPB, 256>>>();
    k_gemm<<<(NN + 127) / 128, 256>>>(x, Wi, bi, 0, wc, nullptr, nullptr);
    for (int l = 0; l < 3; l++) {
        k_agg<<<(NN + WPB - 1) / WPB, 256>>>(bc + l * 64);
        k_gemm<<<(NN + 127) / 128, 256>>>(x, Wl + l * 64 * 128, nullptr, 1,
                                          l < 2 ? wc + (l + 1) * 64 : nullptr,
                                          l == 2 ? Wo : nullptr,
                                          l == 2 ? out : nullptr);
    }
}

// round 8
// speedup vs baseline: 2.9278x; 1.0719x over previous
#include <cuda_runtime.h>
#include <cuda_fp16.h>
#include <cstdint>

#define NN 100000
#define NE 1600000
#define H  64

// ---------------- scratch (device globals; no allocation) ----------------
__device__ __half g_ew[1600000ull * 64];  // edge weights fp16, CSR-slot order [E,64]
__device__ int    g_cnt[NN];
__device__ int    g_off[NN + 1];
__device__ int    g_cur[NN];
__device__ int    g_src[NE];              // CSR-slot -> source node
__device__ int    g_pos[NE];              // edge e -> CSR slot
__device__ float  g_xlin[NN * H];
__device__ float  g_dinv[NN * H];
__device__ __half g_y[NN * H];            // fp16: halves agg gather traffic
__device__ float  g_hagg[NN * H];
__device__ float  g_h[NN * H];

// ---------------- CSR build ----------------
__global__ void k_zero() {
    int i = blockIdx.x * blockDim.x + threadIdx.x;
    if (i < NN) g_cnt[i] = 0;
}

__global__ void k_count(const int* __restrict__ ei) {
    int e = blockIdx.x * blockDim.x + threadIdx.x;
    if (e < NE) {
        int c = ei[NE + e];
        if ((unsigned)c < (unsigned)NN) atomicAdd(&g_cnt[c], 1);
    }
}

__global__ void k_scan() {
    __shared__ int s[1024];
    int t = threadIdx.x;
    const int C = (NN + 1023) / 1024;
    int start = t * C; if (start > NN) start = NN;
    int end = start + C; if (end > NN) end = NN;
    int sum = 0;
    for (int i = start; i < end; i++) sum += g_cnt[i];
    s[t] = sum;
    __syncthreads();
    for (int d = 1; d < 1024; d <<= 1) {
        int v = (t >= d) ? s[t - d] : 0;
        __syncthreads();
        if (t >= d) s[t] += v;
        __syncthreads();
    }
    int run = (t == 0) ? 0 : s[t - 1];
    for (int i = start; i < end; i++) {
        g_off[i] = run; g_cur[i] = run; run += g_cnt[i];
    }
    if (t == 1023) g_off[NN] = run;
}

__global__ void k_fill(const int* __restrict__ ei) {
    int e = blockIdx.x * blockDim.x + threadIdx.x;
    if (e < NE) {
        int c = ei[NE + e];
        int r = ei[e];
        if ((unsigned)c >= (unsigned)NN || (unsigned)r >= (unsigned)NN) return;
        int p = atomicAdd(&g_cur[c], 1);
        g_src[p] = r;          // scattered
        g_pos[e] = p;          // coalesced
    }
}

// ---------------- mma.m16n8k16 f32 += f16 x f16 ----------------
__device__ __forceinline__ void mma16816(float c[4], const uint32_t a[4],
                                         uint32_t b0, uint32_t b1) {
    asm volatile(
        "mma.sync.aligned.m16n8k16.row.col.f32.f16.f16.f32 "
        "{%0,%1,%2,%3}, {%4,%5,%6,%7}, {%8,%9}, {%0,%1,%2,%3};"
        : "+f"(c[0]), "+f"(c[1]), "+f"(c[2]), "+f"(c[3])
        : "r"(a[0]), "r"(a[1]), "r"(a[2]), "r"(a[3]), "r"(b0), "r"(b1));
}

// ---------------- edge MLP (tensor-core): ew = relu( relu(ea@W1^T) @ W2^T ) ----------------
__global__ void __launch_bounds__(256) k_ew(const float* __restrict__ ea,
                                            const float* __restrict__ W1,
                                            const float* __restrict__ W2) {
    __shared__ __half h1s[256][72];
    __shared__ __half w2s[64][72];
    __shared__ float  w1s[64][8];
    __shared__ int    poss[256];
    int t = threadIdx.x;
    for (int i = t; i < 512; i += 256) ((float*)w1s)[i] = W1[i];
    for (int i = t; i < 4096; i += 256) w2s[i >> 6][i & 63] = __float2half(W2[i]);

    int base = blockIdx.x * 256;
    poss[t] = g_pos[base + t];
    float4 a0 = *(const float4*)&ea[(size_t)(base + t) * 8];
    float4 a1 = *(const float4*)&ea[(size_t)(base + t) * 8 + 4];
    __syncthreads();
#pragma unroll
    for (int ch = 0; ch < 64; ch += 2) {
        float4 p0 = *(const float4*)&w1s[ch][0];
        float4 p1 = *(const float4*)&w1s[ch][4];
        float4 q0 = *(const float4*)&w1s[ch + 1][0];
        float4 q1 = *(const float4*)&w1s[ch + 1][4];
        float v0 = a0.x * p0.x + a0.y * p0.y + a0.z * p0.z + a0.w * p0.w
                 + a1.x * p1.x + a1.y * p1.y + a1.z * p1.z + a1.w * p1.w;
        float v1 = a0.x * q0.x + a0.y * q0.y + a0.z * q0.z + a0.w * q0.w
                 + a1.x * q1.x + a1.y * q1.y + a1.z * q1.z + a1.w * q1.w;
        v0 = v0 > 0.f ? v0 : 0.f;
        v1 = v1 > 0.f ? v1 : 0.f;
        *(__half2*)&h1s[t][ch] = __floats2half2_rn(v0, v1);
    }
    __syncthreads();

    int w = t >> 5, l = t & 31;
    float c[2][8][4];
#pragma unroll
    for (int mt = 0; mt < 2; mt++)
#pragma unroll
        for (int nt = 0; nt < 8; nt++)
#pragma unroll
            for (int r = 0; r < 4; r++) c[mt][nt][r] = 0.f;

#pragma unroll
    for (int kc = 0; kc < 4; kc++) {
        int k0 = kc * 16 + (l & 3) * 2;
        uint32_t a[2][4];
#pragma unroll
        for (int mt = 0; mt < 2; mt++) {
            int r = w * 32 + mt * 16 + (l >> 2);
            a[mt][0] = *(const uint32_t*)&h1s[r][k0];
            a[mt][1] = *(const uint32_t*)&h1s[r + 8][k0];
            a[mt][2] = *(const uint32_t*)&h1s[r][k0 + 8];
            a[mt][3] = *(const uint32_t*)&h1s[r + 8][k0 + 8];
        }
#pragma unroll
        for (int nt = 0; nt < 8; nt++) {
            int nr = nt * 8 + (l >> 2);
            uint32_t b0 = *(const uint32_t*)&w2s[nr][k0];
            uint32_t b1 = *(const uint32_t*)&w2s[nr][k0 + 8];
            mma16816(c[0][nt], a[0], b0, b1);
            mma16816(c[1][nt], a[1], b0, b1);
        }
    }

#pragma unroll
    for (int mt = 0; mt < 2; mt++) {
        int m = w * 32 + mt * 16 + (l >> 2);
        size_t row0 = (size_t)poss[m] * 64;
        size_t row1 = (size_t)poss[m + 8] * 64;
#pragma unroll
        for (int nt = 0; nt < 8; nt++) {
            int n = nt * 8 + (l & 3) * 2;
            float v0 = c[mt][nt][0], v1 = c[mt][nt][1];
            float v2 = c[mt][nt][2], v3 = c[mt][nt][3];
            v0 = v0 > 0.f ? v0 : 0.f; v1 = v1 > 0.f ? v1 : 0.f;
            v2 = v2 > 0.f ? v2 : 0.f; v3 = v3 > 0.f ? v3 : 0.f;
            *(__half2*)&g_ew[row0 + n] = __floats2half2_rn(v0, v1);
            *(__half2*)&g_ew[row1 + n] = __floats2half2_rn(v2, v3);
        }
    }
}

// ---------------- degree / dinv (warp per node, half2, unroll 2) ----------------
__global__ void __launch_bounds__(256) k_deg() {
    int w = (blockIdx.x * blockDim.x + threadIdx.x) >> 5;
    int lane = threadIdx.x & 31;
    if (w >= NN) return;
    int s = g_off[w], e = g_off[w + 1];
    const __half2* ewv = (const __half2*)g_ew;
    float2 d0 = make_float2(1.f, 1.f);        // self-loop weight
    float2 d1 = make_float2(0.f, 0.f);
    int p = s;
    for (; p + 2 <= e; p += 2) {
        float2 v0 = __half22float2(ewv[(size_t)p * 32 + lane]);
        float2 v1 = __half22float2(ewv[(size_t)(p + 1) * 32 + lane]);
        d0.x += v0.x; d0.y += v0.y;
        d1.x += v1.x; d1.y += v1.y;
    }
    if (p < e) {
        float2 v0 = __half22float2(ewv[(size_t)p * 32 + lane]);
        d0.x += v0.x; d0.y += v0.y;
    }
    float2 r; r.x = rsqrtf(d0.x + d1.x); r.y = rsqrtf(d0.y + d1.y);
    ((float2*)g_dinv)[(size_t)w * 32 + lane] = r;
}

// ---------------- aggregation (warp per node), unroll 4, int4 src, fp16 y ----------------
__global__ void __launch_bounds__(256) k_agg(const float* __restrict__ bc) {
    int w = (blockIdx.x * blockDim.x + threadIdx.x) >> 5;
    int lane = threadIdx.x & 31;
    if (w >= NN) return;
    int s = g_off[w], e = g_off[w + 1];
    const __half2* yv  = (const __half2*)g_y;
    const __half2* ewv = (const __half2*)g_ew;
    float2 ys = __half22float2(yv[(size_t)w * 32 + lane]);
    float2 a0 = ys;                            // self loop
    float2 a1 = make_float2(0.f, 0.f);
    float2 a2 = make_float2(0.f, 0.f);
    float2 a3 = make_float2(0.f, 0.f);
    int p = s;
    // peel to 16B alignment of g_src
    for (; p < e && (p & 3); p++) {
        int s0 = g_src[p];
        float2 f0 = __half22float2(ewv[(size_t)p * 32 + lane]);
        float2 y0 = __half22float2(yv[(size_t)s0 * 32 + lane]);
        a0.x = fmaf(f0.x, y0.x, a0.x); a0.y = fmaf(f0.y, y0.y, a0.y);
    }
    for (; p + 4 <= e; p += 4) {
        int4 sv = *(const int4*)&g_src[p];
        __half2 h0 = ewv[(size_t)p * 32 + lane];
        __half2 h1 = ewv[(size_t)(p + 1) * 32 + lane];
        __half2 h2 = ewv[(size_t)(p + 2) * 32 + lane];
        __half2 h3 = ewv[(size_t)(p + 3) * 32 + lane];
        float2 y0 = __half22float2(yv[(size_t)sv.x * 32 + lane]);
        float2 y1 = __half22float2(yv[(size_t)sv.y * 32 + lane]);
        float2 y2 = __half22float2(yv[(size_t)sv.z * 32 + lane]);
        float2 y3 = __half22float2(yv[(size_t)sv.w * 32 + lane]);
        float2 f0 = __half22float2(h0), f1 = __half22float2(h1);
        float2 f2 = __half22float2(h2), f3 = __half22float2(h3);
        a0.x = fmaf(f0.x, y0.x, a0.x); a0.y = fmaf(f0.y, y0.y, a0.y);
        a1.x = fmaf(f1.x, y1.x, a1.x); a1.y = fmaf(f1.y, y1.y, a1.y);
        a2.x = fmaf(f2.x, y2.x, a2.x); a2.y = fmaf(f2.y, y2.y, a2.y);
        a3.x = fmaf(f3.x, y3.x, a3.x); a3.y = fmaf(f3.y, y3.y, a3.y);
    }
    for (; p < e; p++) {
        int s0 = g_src[p];
        float2 f0 = __half22float2(ewv[(size_t)p * 32 + lane]);
        float2 y0 = __half22float2(yv[(size_t)s0 * 32 + lane]);
        a0.x = fmaf(f0.x, y0.x, a0.x); a0.y = fmaf(f0.y, y0.y, a0.y);
    }
    float2 dv = ((const float2*)g_dinv)[(size_t)w * 32 + lane];
    float2 r;
    r.x = fmaf(dv.x, (a0.x + a1.x) + (a2.x + a3.x), bc[2 * lane]);
    r.y = fmaf(dv.y, (a0.y + a1.y) + (a2.y + a3.y), bc[2 * lane + 1]);
    ((float2*)g_hagg)[(size_t)w * 32 + lane] = r;
}

// ---------------- tensor-core GEMM: C[N,64] = A[N,128] @ W[64,128]^T ----------------
// mode 0: A0 = xin cols 0-63, A1 = xin cols 64-127 (lda 128), bias=bi, C=g_xlin
// mode 1: A0 = g_xlin, A1 = g_hagg (lda 64), resid=g_xlin, C=g_h
// ywc != null: fused y(fp16) = dinv*relu(C)*ywc.  Wo != null: fused final output.
__global__ void __launch_bounds__(256) k_gemm(const float* __restrict__ xin,
                                              const float* __restrict__ W,
                                              const float* __restrict__ bias,
                                              int mode,
                                              const float* __restrict__ ywc,
                                              const float* __restrict__ Wo,
                                              float* __restrict__ out) {
    __shared__ __half As[128][72];
    __shared__ __half Bs[64][136];
    int t = threadIdx.x;
    for (int i = t; i < 8192; i += 256) Bs[i >> 7][i & 127] = __float2half(W[i]);

    const float *A0, *A1, *resid; float* C; int lda;
    if (mode == 0) { A0 = xin;    A1 = xin + 64; lda = 128; resid = 0;      C = g_xlin; }
    else           { A0 = g_xlin; A1 = g_hagg;   lda = 64;  resid = g_xlin; C = g_h;    }

    int bm = blockIdx.x * 128;
    int w = t >> 5, l = t & 31;
    float c[8][4];
#pragma unroll
    for (int nt = 0; nt < 8; nt++)
#pragma unroll
        for (int r = 0; r < 4; r++) c[nt][r] = 0.f;

    int lrow = t >> 1, lc0 = (t & 1) * 32;
    bool lvalid = (bm + lrow) < NN;

#pragma unroll
    for (int pass = 0; pass < 2; pass++) {
        const float* A = pass ? A1 : A0;
        __syncthreads();
        const float* srcp = &A[(size_t)(bm + lrow) * lda + lc0];
#pragma unroll
        for (int ch = 0; ch < 4; ch++) {
            float4 v0 = make_float4(0.f, 0.f, 0.f, 0.f), v1 = v0;
            if (lvalid) {
                v0 = *(const float4*)&srcp[ch * 8];
                v1 = *(const float4*)&srcp[ch * 8 + 4];
            }
            __half2 h0 = __floats2half2_rn(v0.x, v0.y);
            __half2 h1 = __floats2half2_rn(v0.z, v0.w);
            __half2 h2 = __floats2half2_rn(v1.x, v1.y);
            __half2 h3 = __floats2half2_rn(v1.z, v1.w);
            uint4 pk;
            pk.x = *(uint32_t*)&h0; pk.y = *(uint32_t*)&h1;
            pk.z = *(uint32_t*)&h2; pk.w = *(uint32_t*)&h3;
            *(uint4*)&As[lrow][lc0 + ch * 8] = pk;
        }
        __syncthreads();
#pragma unroll
        for (int kc = 0; kc < 4; kc++) {
            int k0 = kc * 16 + (l & 3) * 2;
            int row = w * 16 + (l >> 2);
            uint32_t a[4];
            a[0] = *(const uint32_t*)&As[row][k0];
            a[1] = *(const uint32_t*)&As[row + 8][k0];
            a[2] = *(const uint32_t*)&As[row][k0 + 8];
            a[3] = *(const uint32_t*)&As[row + 8][k0 + 8];
            int kb = pass * 64 + k0;
#pragma unroll
            for (int nt = 0; nt < 8; nt++) {
                int nr = nt * 8 + (l >> 2);
                uint32_t b0 = *(const uint32_t*)&Bs[nr][kb];
                uint32_t b1 = *(const uint32_t*)&Bs[nr][kb + 8];
                mma16816(c[nt], a, b0, b1);
            }
        }
    }

    int m0 = bm + w * 16 + (l >> 2);
    int n0 = (l & 3) * 2;

    if (Wo) {
        float oacc[2] = {0.f, 0.f};
#pragma unroll
        for (int nt = 0; nt < 8; nt++) {
            int n = nt * 8 + n0;
            float wx0 = Wo[n], wx1 = Wo[n + 1];
            float wh0 = Wo[64 + n], wh1 = Wo[64 + n + 1];
#pragma unroll
            for (int rr = 0; rr < 2; rr++) {
                int m = m0 + rr * 8;
                if (m >= NN) continue;
                float2 rv = *(const float2*)&resid[(size_t)m * 64 + n];
                float h0 = c[nt][rr * 2] + rv.x;
                float h1 = c[nt][rr * 2 + 1] + rv.y;
                h0 = h0 > 0.f ? h0 : 0.f;
                h1 = h1 > 0.f ? h1 : 0.f;
                oacc[rr] += rv.x * wx0 + rv.y * wx1 + h0 * wh0 + h1 * wh1;
            }
        }
#pragma unroll
        for (int rr = 0; rr < 2; rr++) {
            oacc[rr] += __shfl_xor_sync(0xffffffffu, oacc[rr], 1);
            oacc[rr] += __shfl_xor_sync(0xffffffffu, oacc[rr], 2);
        }
        if ((l & 3) == 0) {
            if (m0 < NN)     out[m0]     = oacc[0];
            if (m0 + 8 < NN) out[m0 + 8] = oacc[1];
        }
        return;
    }

#pragma unroll
    for (int nt = 0; nt < 8; nt++) {
        int n = nt * 8 + n0;
#pragma unroll
        for (int rr = 0; rr < 2; rr++) {
            int m = m0 + rr * 8;
            if (m >= NN) continue;
            float v0 = c[nt][rr * 2], v1 = c[nt][rr * 2 + 1];
            if (bias) { v0 += bias[n]; v1 += bias[n + 1]; }
            if (resid) {
                float2 rv = *(const float2*)&resid[(size_t)m * 64 + n];
                v0 += rv.x; v1 += rv.y;
            }
            float2 ov; ov.x = v0; ov.y = v1;
            *(float2*)&C[(size_t)m * 64 + n] = ov;
            if (ywc) {
                float2 dv = *(const float2*)&g_dinv[(size_t)m * 64 + n];
                float r0 = v0 > 0.f ? v0 : 0.f;
                float r1 = v1 > 0.f ? v1 : 0.f;
                *(__half2*)&g_y[(size_t)m * 64 + n] =
                    __floats2half2_rn(dv.x * r0 * ywc[n], dv.y * r1 * ywc[n + 1]);
            }
        }
    }
}

// ---------------- host ----------------
extern "C" void kernel_launch(void* const* d_in, const int* in_sizes, int n_in,
                              void* d_out, int out_size) {
    const float* x  = (const float*)d_in[0];
    const int*   ei = (const int*)d_in[1];     // int32 [2, E]
    const float* ea = (const float*)d_in[2];
    const float* W1 = (const float*)d_in[3];
    const float* W2 = (const float*)d_in[4];
    const float* Wi = (const float*)d_in[5];
    const float* bi = (const float*)d_in[6];
    const float* wc = (const float*)d_in[7];
    const float* bc = (const float*)d_in[8];
    const float* Wl = (const float*)d_in[9];
    const float* Wo = (const float*)d_in[10];
    float* out = (float*)d_out;

    const int WPB = 8;
    k_zero<<<(NN + 1023) / 1024, 1024>>>();
    k_count<<<(NE + 255) / 256, 256>>>(ei);
    k_scan<<<1, 1024>>>();
    k_fill<<<(NE + 255) / 256, 256>>>(ei);
    k_ew<<<NE / 256, 256>>>(ea, W1, W2);
    k_deg<<<(NN + WPB - 1) / WPB, 256>>>();
    k_gemm<<<(NN + 127) / 128, 256>>>(x, Wi, bi, 0, wc, nullptr, nullptr);
    for (int l = 0; l < 3; l++) {
        k_agg<<<(NN + WPB - 1) / WPB, 256>>>(bc + l * 64);
        k_gemm<<<(NN + 127) / 128, 256>>>(x, Wl + l * 64 * 128, nullptr, 1,
                                          l < 2 ? wc + (l + 1) * 64 : nullptr,
                                          l == 2 ? Wo : nullptr,
                                          l == 2 ? out : nullptr);
    }
}